// round 2
// baseline (speedup 1.0000x reference)
#include <cuda_runtime.h>

#define N_NODES 100000
#define N_EDGES 1600000
#define D_F     128
#define D_CAT   256
#define D_U1    214
#define D_U2    172
#define D_OUT   128

#define EDGE_BLOCKS 800
#define EDGES_PER_BLOCK 2000   // 800 * 2000 = 1,600,000 exactly
#define ET 16                  // edge tile per iteration
#define H_STRIDE 20            // padded row stride for h buffers (float4-aligned)

// ---------------- scratch (device globals; no allocation allowed) ----------------
__device__ float g_aggr[N_NODES * D_F];      // 51.2 MB
__device__ float g_nrm [N_NODES * D_CAT];    // 102.4 MB
__device__ float g_u1  [N_NODES * D_U1];     // 85.6 MB
__device__ float g_u2  [N_NODES * D_U2];     // 68.8 MB

// ---------------- helpers ----------------
__device__ __forceinline__ float leaky(float v) { return v > 0.f ? v : 0.01f * v; }

__device__ __forceinline__ unsigned long long pk(float x, float y) {
    unsigned long long r;
    asm("mov.b64 %0, {%1, %2};" : "=l"(r) : "f"(x), "f"(y));
    return r;
}
__device__ __forceinline__ float2 upk(unsigned long long v) {
    float2 f;
    asm("mov.b64 {%0, %1}, %2;" : "=f"(f.x), "=f"(f.y) : "l"(v));
    return f;
}
__device__ __forceinline__ unsigned long long fma2(unsigned long long a,
                                                   unsigned long long b,
                                                   unsigned long long c) {
    unsigned long long d;
    asm("fma.rn.f32x2 %0, %1, %2, %3;" : "=l"(d) : "l"(a), "l"(b), "l"(c));
    return d;
}

// ---------------- kernel: zero aggr scratch ----------------
__global__ void k_zero() {
    const int n4 = (N_NODES * D_F) / 4;
    float4* p = reinterpret_cast<float4*>(g_aggr);
    for (int i = blockIdx.x * blockDim.x + threadIdx.x; i < n4; i += gridDim.x * blockDim.x)
        p[i] = make_float4(0.f, 0.f, 0.f, 0.f);
}

// ---------------- kernel: edge MLP + scatter-add ----------------
// 256 threads: f = tid & 127 (feature), g = tid >> 7 (edge half-tile).
__global__ void __launch_bounds__(256, 1)
k_edge(const float* __restrict__ edge_attr,
       const int* __restrict__ edge_index,          // int32! harness converts int64 -> int32
       const float* __restrict__ Wm1, const float* __restrict__ bm1,
       const float* __restrict__ Wm2, const float* __restrict__ bm2,
       const float* __restrict__ Wm3, const float* __restrict__ bm3)
{
    extern __shared__ char smraw[];
    int* dsts = reinterpret_cast<int*>(smraw);                     // 16 * 4 = 64 B (pad to 128)
    float* smf = reinterpret_cast<float*>(smraw + 128);
    float* W2  = smf;                    // 128*129 = 16512 floats
    float* W3  = smf + 16512;            // 16512 floats
    float* h1s = smf + 33024;            // 128*20 = 2560
    float* h2s = h1s + 2560;             // 2560
    float* eas = h2s + 2560;             // 80

    const int tid = threadIdx.x;
    const int f = tid & 127;
    const int g = tid >> 7;

    // transposed weight staging (conflict-free: stride 129)
    for (int i = tid; i < 128 * 128; i += 256) {
        const int ff = i >> 7, kk = i & 127;
        W2[kk * 129 + ff] = Wm2[i];
        W3[kk * 129 + ff] = Wm3[i];
    }
    float w1[5];
#pragma unroll
    for (int j = 0; j < 5; j++) w1[j] = Wm1[f * 5 + j];
    const float b1 = bm1[f], b2 = bm2[f], b3 = bm3[f];
    __syncthreads();

    const int e0blk = blockIdx.x * EDGES_PER_BLOCK;

    for (int t = 0; t < EDGES_PER_BLOCK; t += ET) {
        __syncthreads();   // protect dsts/eas from previous iteration's readers
        const int e0 = e0blk + t;
        if (tid < ET * 5) eas[tid] = edge_attr[(long long)e0 * 5 + tid];
        if (tid < ET)     dsts[tid] = edge_index[N_EDGES + e0 + tid];
        __syncthreads();

        // ---- layer 1: 5 -> 128 ----
        {
            float v[8];
#pragma unroll
            for (int i = 0; i < 8; i++) {
                const int e = g * 8 + i;
                float a = b1;
#pragma unroll
                for (int j = 0; j < 5; j++) a = fmaf(w1[j], eas[e * 5 + j], a);
                v[i] = leaky(a);
            }
            *reinterpret_cast<float4*>(&h1s[f * H_STRIDE + g * 8])     = make_float4(v[0], v[1], v[2], v[3]);
            *reinterpret_cast<float4*>(&h1s[f * H_STRIDE + g * 8 + 4]) = make_float4(v[4], v[5], v[6], v[7]);
        }
        __syncthreads();

        // ---- layer 2: 128 -> 128 ----
        {
            unsigned long long a0 = pk(b2, b2), a1 = a0, a2 = a0, a3 = a0;
#pragma unroll 8
            for (int k = 0; k < 128; k++) {
                const float w = W2[k * 129 + f];
                const unsigned long long ww = pk(w, w);
                const ulonglong2 ha = *reinterpret_cast<const ulonglong2*>(&h1s[k * H_STRIDE + g * 8]);
                const ulonglong2 hb = *reinterpret_cast<const ulonglong2*>(&h1s[k * H_STRIDE + g * 8 + 4]);
                a0 = fma2(ww, ha.x, a0);
                a1 = fma2(ww, ha.y, a1);
                a2 = fma2(ww, hb.x, a2);
                a3 = fma2(ww, hb.y, a3);
            }
            const float2 v0 = upk(a0), v1 = upk(a1), v2 = upk(a2), v3 = upk(a3);
            *reinterpret_cast<float4*>(&h2s[f * H_STRIDE + g * 8]) =
                make_float4(leaky(v0.x), leaky(v0.y), leaky(v1.x), leaky(v1.y));
            *reinterpret_cast<float4*>(&h2s[f * H_STRIDE + g * 8 + 4]) =
                make_float4(leaky(v2.x), leaky(v2.y), leaky(v3.x), leaky(v3.y));
        }
        __syncthreads();

        // ---- layer 3: 128 -> 128, then scatter-add ----
        {
            unsigned long long a0 = pk(b3, b3), a1 = a0, a2 = a0, a3 = a0;
#pragma unroll 8
            for (int k = 0; k < 128; k++) {
                const float w = W3[k * 129 + f];
                const unsigned long long ww = pk(w, w);
                const ulonglong2 ha = *reinterpret_cast<const ulonglong2*>(&h2s[k * H_STRIDE + g * 8]);
                const ulonglong2 hb = *reinterpret_cast<const ulonglong2*>(&h2s[k * H_STRIDE + g * 8 + 4]);
                a0 = fma2(ww, ha.x, a0);
                a1 = fma2(ww, ha.y, a1);
                a2 = fma2(ww, hb.x, a2);
                a3 = fma2(ww, hb.y, a3);
            }
            const float2 v0 = upk(a0), v1 = upk(a1), v2 = upk(a2), v3 = upk(a3);
            const float mv[8] = {v0.x, v0.y, v1.x, v1.y, v2.x, v2.y, v3.x, v3.y};
#pragma unroll
            for (int i = 0; i < 8; i++) {
                const int d = dsts[g * 8 + i];
                atomicAdd(&g_aggr[(long long)d * D_F + f], mv[i]);
            }
        }
    }
}

// ---------------- kernel: LayerNorm over concat(x, aggr) ----------------
// one warp per node
__global__ void k_ln(const float* __restrict__ x,
                     const float* __restrict__ ln_g,
                     const float* __restrict__ ln_b)
{
    const int node = (blockIdx.x * blockDim.x + threadIdx.x) >> 5;
    const int lane = threadIdx.x & 31;
    if (node >= N_NODES) return;

    const float* xr = x      + (long long)node * D_F;
    const float* ar = g_aggr + (long long)node * D_F;
    float v[8];
#pragma unroll
    for (int i = 0; i < 4; i++) v[i]     = xr[lane + 32 * i];
#pragma unroll
    for (int i = 0; i < 4; i++) v[4 + i] = ar[lane + 32 * i];

    float s = 0.f;
#pragma unroll
    for (int i = 0; i < 8; i++) s += v[i];
#pragma unroll
    for (int o = 16; o > 0; o >>= 1) s += __shfl_xor_sync(0xffffffffu, s, o);
    const float mu = s * (1.0f / 256.0f);

    float q = 0.f;
#pragma unroll
    for (int i = 0; i < 8; i++) { const float d = v[i] - mu; q += d * d; }
#pragma unroll
    for (int o = 16; o > 0; o >>= 1) q += __shfl_xor_sync(0xffffffffu, q, o);
    const float rstd = rsqrtf(q * (1.0f / 256.0f) + 1e-5f);

    float* out = g_nrm + (long long)node * D_CAT;
#pragma unroll
    for (int i = 0; i < 8; i++) {
        const int c = (i < 4) ? (lane + 32 * i) : (128 + lane + 32 * (i - 4));
        out[c] = (v[i] - mu) * rstd * ln_g[c] + ln_b[c];
    }
}

// ---------------- kernel: generic fused GEMM  C = post(A[M,K] @ B[N,K]^T + bias) ----------------
// 64x64 tile, 256 threads, 4x4 microtile. tx (tid&15) -> n dim, ty (tid>>4) -> m dim.
__global__ void __launch_bounds__(256)
k_gemm(const float* __restrict__ A, const float* __restrict__ B,
       const float* __restrict__ bias, float* __restrict__ C,
       int M, int N, int K, int doLeaky)
{
    __shared__ float As[16][68];
    __shared__ float Bs[16][68];

    const int tid = threadIdx.x;
    const int tx = tid & 15;   // n-quad
    const int ty = tid >> 4;   // m-quad
    const int m0 = blockIdx.x * 64;
    const int n0 = blockIdx.y * 64;

    unsigned long long acc[4][2];
#pragma unroll
    for (int i = 0; i < 4; i++) { acc[i][0] = pk(0.f, 0.f); acc[i][1] = pk(0.f, 0.f); }

    for (int k0 = 0; k0 < K; k0 += 16) {
#pragma unroll
        for (int r = 0; r < 4; r++) {
            const int i = tid + r * 256;
            const int mm = i >> 4, kk = i & 15;
            const int ka = k0 + kk;
            const int ma = m0 + mm;
            const int na = n0 + mm;
            As[kk][mm] = (ma < M && ka < K) ? A[(long long)ma * K + ka] : 0.f;
            Bs[kk][mm] = (na < N && ka < K) ? B[(long long)na * K + ka] : 0.f;
        }
        __syncthreads();
#pragma unroll
        for (int kk = 0; kk < 16; kk++) {
            const float4 a4 = *reinterpret_cast<const float4*>(&As[kk][ty * 4]);
            const ulonglong2 b2 = *reinterpret_cast<const ulonglong2*>(&Bs[kk][tx * 4]);
            const float av[4] = {a4.x, a4.y, a4.z, a4.w};
#pragma unroll
            for (int i = 0; i < 4; i++) {
                const unsigned long long aa = pk(av[i], av[i]);
                acc[i][0] = fma2(b2.x, aa, acc[i][0]);
                acc[i][1] = fma2(b2.y, aa, acc[i][1]);
            }
        }
        __syncthreads();
    }

    const int nb = n0 + tx * 4;
#pragma unroll
    for (int i = 0; i < 4; i++) {
        const int m = m0 + ty * 4 + i;
        if (m >= M) continue;
        const float2 c0 = upk(acc[i][0]);
        const float2 c1 = upk(acc[i][1]);
        float cv[4] = {c0.x, c0.y, c1.x, c1.y};
#pragma unroll
        for (int j = 0; j < 4; j++) {
            const int n = nb + j;
            if (n < N) {
                float val = cv[j] + bias[n];
                if (doLeaky) val = leaky(val);
                C[(long long)m * N + n] = val;
            }
        }
    }
}

// ---------------- launch ----------------
extern "C" void kernel_launch(void* const* d_in, const int* in_sizes, int n_in,
                              void* d_out, int out_size)
{
    const float* x          = (const float*)d_in[0];
    const int*   edge_index = (const int*)d_in[1];
    const float* edge_attr  = (const float*)d_in[2];
    const float* Wm1 = (const float*)d_in[3];
    const float* bm1 = (const float*)d_in[4];
    const float* Wm2 = (const float*)d_in[5];
    const float* bm2 = (const float*)d_in[6];
    const float* Wm3 = (const float*)d_in[7];
    const float* bm3 = (const float*)d_in[8];
    const float* ln_g = (const float*)d_in[9];
    const float* ln_b = (const float*)d_in[10];
    const float* Wu1 = (const float*)d_in[11];
    const float* bu1 = (const float*)d_in[12];
    const float* Wu2 = (const float*)d_in[13];
    const float* bu2 = (const float*)d_in[14];
    const float* Wu3 = (const float*)d_in[15];
    const float* bu3 = (const float*)d_in[16];
    float* out = (float*)d_out;

    void *p_nrm = nullptr, *p_u1 = nullptr, *p_u2 = nullptr;
    cudaGetSymbolAddress(&p_nrm, g_nrm);
    cudaGetSymbolAddress(&p_u1,  g_u1);
    cudaGetSymbolAddress(&p_u2,  g_u2);

    const int edge_smem = 128 + (16512 + 16512 + 2560 + 2560 + 80) * 4;  // 153,024 B
    cudaFuncSetAttribute(k_edge, cudaFuncAttributeMaxDynamicSharedMemorySize, edge_smem);

    k_zero<<<2048, 256>>>();

    k_edge<<<EDGE_BLOCKS, 256, edge_smem>>>(edge_attr, edge_index,
                                            Wm1, bm1, Wm2, bm2, Wm3, bm3);

    k_ln<<<(N_NODES * 32 + 255) / 256, 256>>>(x, ln_g, ln_b);

    dim3 g1((N_NODES + 63) / 64, (D_U1 + 63) / 64);
    k_gemm<<<g1, 256>>>((const float*)p_nrm, Wu1, bu1, (float*)p_u1,
                        N_NODES, D_U1, D_CAT, 1);

    dim3 g2((N_NODES + 63) / 64, (D_U2 + 63) / 64);
    k_gemm<<<g2, 256>>>((const float*)p_u1, Wu2, bu2, (float*)p_u2,
                        N_NODES, D_U2, D_U1, 1);

    dim3 g3((N_NODES + 63) / 64, (D_OUT + 63) / 64);
    k_gemm<<<g3, 256>>>((const float*)p_u2, Wu3, bu3, out,
                        N_NODES, D_OUT, D_U2, 0);
}

// round 3
// speedup vs baseline: 1.4338x; 1.4338x over previous
#include <cuda_runtime.h>

#define N_NODES 100000
#define N_EDGES 1600000
#define D_F     128
#define D_CAT   256
#define D_U1    214
#define D_U2    172
#define D_OUT   128

// ---- edge kernel tiling ----
#define E_TILE   64                 // edges per tile
#define N_TILES  (N_EDGES / E_TILE) // 25000
#define HS 68                       // h buffer row stride (floats)
#define WS 132                      // weight row stride (floats)

// smem float offsets (k_edge)
#define OFF_W2   0
#define OFF_W3   (OFF_W2 + 128 * WS)     // 16896
#define OFF_H1   (OFF_W3 + 128 * WS)     // 33792
#define OFF_H2   (OFF_H1 + 128 * HS)     // 42496
#define OFF_W1   (OFF_H2 + 128 * HS)     // 51200
#define OFF_B1   (OFF_W1 + 640)          // 51840
#define OFF_B2   (OFF_B1 + 128)
#define OFF_B3   (OFF_B2 + 128)
#define OFF_EA   (OFF_B3 + 128)          // 52224
#define OFF_DST  (OFF_EA + 320)          // 52544
#define EDGE_SMEM_FLOATS (OFF_DST + 64)  // 52608 floats = 210,432 B

// ---------------- scratch (device globals; no allocation allowed) ----------------
__device__ float g_aggr[N_NODES * D_F];      // 51.2 MB
__device__ float g_nrm [N_NODES * D_CAT];    // 102.4 MB
__device__ float g_u1  [N_NODES * D_U1];     // 85.6 MB
__device__ float g_u2  [N_NODES * D_U2];     // 68.8 MB

// ---------------- helpers ----------------
__device__ __forceinline__ float leaky(float v) { return v > 0.f ? v : 0.01f * v; }

__device__ __forceinline__ unsigned long long pk(float x, float y) {
    unsigned long long r;
    asm("mov.b64 %0, {%1, %2};" : "=l"(r) : "f"(x), "f"(y));
    return r;
}
__device__ __forceinline__ float2 upk(unsigned long long v) {
    float2 f;
    asm("mov.b64 {%0, %1}, %2;" : "=f"(f.x), "=f"(f.y) : "l"(v));
    return f;
}
__device__ __forceinline__ unsigned long long fma2(unsigned long long a,
                                                   unsigned long long b,
                                                   unsigned long long c) {
    unsigned long long d;
    asm("fma.rn.f32x2 %0, %1, %2, %3;" : "=l"(d) : "l"(a), "l"(b), "l"(c));
    return d;
}

// ---------------- kernel: zero aggr scratch ----------------
__global__ void k_zero() {
    const int n4 = (N_NODES * D_F) / 4;
    float4* p = reinterpret_cast<float4*>(g_aggr);
    for (int i = blockIdx.x * blockDim.x + threadIdx.x; i < n4; i += gridDim.x * blockDim.x)
        p[i] = make_float4(0.f, 0.f, 0.f, 0.f);
}

// ---------------- edge layer: 128->128 GEMM over 64-edge tile ----------------
// thread (fg, eg): 8 features (fg*8..) x 4 edges (eg*4..), accumulators packed over f-pairs.
template <bool FINAL>
__device__ __forceinline__ void edge_layer(
    const float* __restrict__ Wt,    // smem [k][f], stride WS
    const float* __restrict__ hin,   // smem [k][e], stride HS
    const float* __restrict__ bs,    // smem bias [128]
    float* __restrict__ hout,        // smem [f][e], stride HS (if !FINAL)
    const int* __restrict__ dsti,    // smem dst [64] (if FINAL)
    int fg, int eg)
{
    const int f0 = fg * 8;
    const unsigned long long b01 = pk(bs[f0],     bs[f0 + 1]);
    const unsigned long long b23 = pk(bs[f0 + 2], bs[f0 + 3]);
    const unsigned long long b45 = pk(bs[f0 + 4], bs[f0 + 5]);
    const unsigned long long b67 = pk(bs[f0 + 6], bs[f0 + 7]);

    unsigned long long acc[4][4];
#pragma unroll
    for (int ei = 0; ei < 4; ei++) {
        acc[ei][0] = b01; acc[ei][1] = b23; acc[ei][2] = b45; acc[ei][3] = b67;
    }

#pragma unroll 4
    for (int k = 0; k < 128; k++) {
        const ulonglong2 wA = *reinterpret_cast<const ulonglong2*>(&Wt[k * WS + f0]);
        const ulonglong2 wB = *reinterpret_cast<const ulonglong2*>(&Wt[k * WS + f0 + 4]);
        const float4 hv = *reinterpret_cast<const float4*>(&hin[k * HS + eg * 4]);
        const float he[4] = {hv.x, hv.y, hv.z, hv.w};
#pragma unroll
        for (int ei = 0; ei < 4; ei++) {
            const unsigned long long hh = pk(he[ei], he[ei]);
            acc[ei][0] = fma2(wA.x, hh, acc[ei][0]);
            acc[ei][1] = fma2(wA.y, hh, acc[ei][1]);
            acc[ei][2] = fma2(wB.x, hh, acc[ei][2]);
            acc[ei][3] = fma2(wB.y, hh, acc[ei][3]);
        }
    }

    if (!FINAL) {
#pragma unroll
        for (int ei = 0; ei < 4; ei++) {
            const int e = eg * 4 + ei;
#pragma unroll
            for (int fp = 0; fp < 4; fp++) {
                const float2 v = upk(acc[ei][fp]);
                const int f = f0 + fp * 2;
                hout[f * HS + e]       = leaky(v.x);
                hout[(f + 1) * HS + e] = leaky(v.y);
            }
        }
    } else {
#pragma unroll
        for (int ei = 0; ei < 4; ei++) {
            const int e = eg * 4 + ei;
            const int d = dsti[e];
            float* p = &g_aggr[(long long)d * D_F + f0];
            const float2 v0 = upk(acc[ei][0]);
            const float2 v1 = upk(acc[ei][1]);
            const float2 v2 = upk(acc[ei][2]);
            const float2 v3 = upk(acc[ei][3]);
            atomicAdd(p + 0, v0.x); atomicAdd(p + 1, v0.y);
            atomicAdd(p + 2, v1.x); atomicAdd(p + 3, v1.y);
            atomicAdd(p + 4, v2.x); atomicAdd(p + 5, v2.y);
            atomicAdd(p + 6, v3.x); atomicAdd(p + 7, v3.y);
        }
    }
}

// ---------------- kernel: edge MLP + scatter-add (persistent, 148 blocks) ----------------
__global__ void __launch_bounds__(256, 1)
k_edge(const float* __restrict__ edge_attr,
       const int* __restrict__ edge_index,          // int32 (harness converts int64 -> int32)
       const float* __restrict__ Wm1, const float* __restrict__ bm1,
       const float* __restrict__ Wm2, const float* __restrict__ bm2,
       const float* __restrict__ Wm3, const float* __restrict__ bm3)
{
    extern __shared__ float sm[];
    float* W2T = sm + OFF_W2;
    float* W3T = sm + OFF_W3;
    float* h1  = sm + OFF_H1;
    float* h2  = sm + OFF_H2;
    float* w1s = sm + OFF_W1;
    float* b1s = sm + OFF_B1;
    float* b2s = sm + OFF_B2;
    float* b3s = sm + OFF_B3;
    float* eas = sm + OFF_EA;
    int*   dsti = reinterpret_cast<int*>(sm + OFF_DST);

    const int tid = threadIdx.x;
    const int fg = tid >> 4;   // 0..15 : feature group (8 features)
    const int eg = tid & 15;   // 0..15 : edge group (4 edges)

    // stage weights transposed [k][f]
    for (int i = tid; i < 128 * 128; i += 256) {
        const int f = i >> 7, k = i & 127;
        W2T[k * WS + f] = Wm2[i];
        W3T[k * WS + f] = Wm3[i];
    }
    for (int i = tid; i < 640; i += 256) w1s[i] = Wm1[i];
    if (tid < 128) { b1s[tid] = bm1[tid]; b2s[tid] = bm2[tid]; b3s[tid] = bm3[tid]; }
    __syncthreads();

    for (int tile = blockIdx.x; tile < N_TILES; tile += gridDim.x) {
        const long long e0 = (long long)tile * E_TILE;
        __syncthreads();   // protect eas/dsti from previous tile's readers
        for (int i = tid; i < E_TILE * 5; i += 256) eas[i] = edge_attr[e0 * 5 + i];
        if (tid < E_TILE) dsti[tid] = edge_index[N_EDGES + e0 + tid];
        __syncthreads();

        // ---- layer 1: 5 -> 128 (writes h1[f][e]) ----
        {
            const int f0 = fg * 8;
#pragma unroll
            for (int ei = 0; ei < 4; ei++) {
                const int e = eg * 4 + ei;
                const float a0 = eas[e * 5 + 0];
                const float a1 = eas[e * 5 + 1];
                const float a2 = eas[e * 5 + 2];
                const float a3 = eas[e * 5 + 3];
                const float a4 = eas[e * 5 + 4];
#pragma unroll
                for (int i = 0; i < 8; i++) {
                    const int f = f0 + i;
                    float v = b1s[f];
                    v = fmaf(w1s[f * 5 + 0], a0, v);
                    v = fmaf(w1s[f * 5 + 1], a1, v);
                    v = fmaf(w1s[f * 5 + 2], a2, v);
                    v = fmaf(w1s[f * 5 + 3], a3, v);
                    v = fmaf(w1s[f * 5 + 4], a4, v);
                    h1[f * HS + e] = leaky(v);
                }
            }
        }
        __syncthreads();

        // ---- layer 2: 128 -> 128 ----
        edge_layer<false>(W2T, h1, b2s, h2, nullptr, fg, eg);
        __syncthreads();

        // ---- layer 3: 128 -> 128 + scatter-add ----
        edge_layer<true>(W3T, h2, b3s, nullptr, dsti, fg, eg);
    }
}

// ---------------- kernel: LayerNorm over concat(x, aggr) ----------------
__global__ void k_ln(const float* __restrict__ x,
                     const float* __restrict__ ln_g,
                     const float* __restrict__ ln_b)
{
    const int node = (blockIdx.x * blockDim.x + threadIdx.x) >> 5;
    const int lane = threadIdx.x & 31;
    if (node >= N_NODES) return;

    const float* xr = x      + (long long)node * D_F;
    const float* ar = g_aggr + (long long)node * D_F;
    float v[8];
#pragma unroll
    for (int i = 0; i < 4; i++) v[i]     = xr[lane + 32 * i];
#pragma unroll
    for (int i = 0; i < 4; i++) v[4 + i] = ar[lane + 32 * i];

    float s = 0.f;
#pragma unroll
    for (int i = 0; i < 8; i++) s += v[i];
#pragma unroll
    for (int o = 16; o > 0; o >>= 1) s += __shfl_xor_sync(0xffffffffu, s, o);
    const float mu = s * (1.0f / 256.0f);

    float q = 0.f;
#pragma unroll
    for (int i = 0; i < 8; i++) { const float d = v[i] - mu; q += d * d; }
#pragma unroll
    for (int o = 16; o > 0; o >>= 1) q += __shfl_xor_sync(0xffffffffu, q, o);
    const float rstd = rsqrtf(q * (1.0f / 256.0f) + 1e-5f);

    float* out = g_nrm + (long long)node * D_CAT;
#pragma unroll
    for (int i = 0; i < 8; i++) {
        const int c = (i < 4) ? (lane + 32 * i) : (128 + lane + 32 * (i - 4));
        out[c] = (v[i] - mu) * rstd * ln_g[c] + ln_b[c];
    }
}

// ---------------- kernel: generic fused GEMM  C = post(A[M,K] @ B[N,K]^T + bias) ----------------
__global__ void __launch_bounds__(256)
k_gemm(const float* __restrict__ A, const float* __restrict__ B,
       const float* __restrict__ bias, float* __restrict__ C,
       int M, int N, int K, int doLeaky)
{
    __shared__ float As[16][68];
    __shared__ float Bs[16][68];

    const int tid = threadIdx.x;
    const int tx = tid & 15;
    const int ty = tid >> 4;
    const int m0 = blockIdx.x * 64;
    const int n0 = blockIdx.y * 64;

    unsigned long long acc[4][2];
#pragma unroll
    for (int i = 0; i < 4; i++) { acc[i][0] = pk(0.f, 0.f); acc[i][1] = pk(0.f, 0.f); }

    for (int k0 = 0; k0 < K; k0 += 16) {
#pragma unroll
        for (int r = 0; r < 4; r++) {
            const int i = tid + r * 256;
            const int mm = i >> 4, kk = i & 15;
            const int ka = k0 + kk;
            const int ma = m0 + mm;
            const int na = n0 + mm;
            As[kk][mm] = (ma < M && ka < K) ? A[(long long)ma * K + ka] : 0.f;
            Bs[kk][mm] = (na < N && ka < K) ? B[(long long)na * K + ka] : 0.f;
        }
        __syncthreads();
#pragma unroll
        for (int kk = 0; kk < 16; kk++) {
            const float4 a4 = *reinterpret_cast<const float4*>(&As[kk][ty * 4]);
            const ulonglong2 b2 = *reinterpret_cast<const ulonglong2*>(&Bs[kk][tx * 4]);
            const float av[4] = {a4.x, a4.y, a4.z, a4.w};
#pragma unroll
            for (int i = 0; i < 4; i++) {
                const unsigned long long aa = pk(av[i], av[i]);
                acc[i][0] = fma2(b2.x, aa, acc[i][0]);
                acc[i][1] = fma2(b2.y, aa, acc[i][1]);
            }
        }
        __syncthreads();
    }

    const int nb = n0 + tx * 4;
#pragma unroll
    for (int i = 0; i < 4; i++) {
        const int m = m0 + ty * 4 + i;
        if (m >= M) continue;
        const float2 c0 = upk(acc[i][0]);
        const float2 c1 = upk(acc[i][1]);
        float cv[4] = {c0.x, c0.y, c1.x, c1.y};
#pragma unroll
        for (int j = 0; j < 4; j++) {
            const int n = nb + j;
            if (n < N) {
                float val = cv[j] + bias[n];
                if (doLeaky) val = leaky(val);
                C[(long long)m * N + n] = val;
            }
        }
    }
}

// ---------------- launch ----------------
extern "C" void kernel_launch(void* const* d_in, const int* in_sizes, int n_in,
                              void* d_out, int out_size)
{
    const float* x          = (const float*)d_in[0];
    const int*   edge_index = (const int*)d_in[1];
    const float* edge_attr  = (const float*)d_in[2];
    const float* Wm1 = (const float*)d_in[3];
    const float* bm1 = (const float*)d_in[4];
    const float* Wm2 = (const float*)d_in[5];
    const float* bm2 = (const float*)d_in[6];
    const float* Wm3 = (const float*)d_in[7];
    const float* bm3 = (const float*)d_in[8];
    const float* ln_g = (const float*)d_in[9];
    const float* ln_b = (const float*)d_in[10];
    const float* Wu1 = (const float*)d_in[11];
    const float* bu1 = (const float*)d_in[12];
    const float* Wu2 = (const float*)d_in[13];
    const float* bu2 = (const float*)d_in[14];
    const float* Wu3 = (const float*)d_in[15];
    const float* bu3 = (const float*)d_in[16];
    float* out = (float*)d_out;

    void *p_nrm = nullptr, *p_u1 = nullptr, *p_u2 = nullptr;
    cudaGetSymbolAddress(&p_nrm, g_nrm);
    cudaGetSymbolAddress(&p_u1,  g_u1);
    cudaGetSymbolAddress(&p_u2,  g_u2);

    const int edge_smem = EDGE_SMEM_FLOATS * 4;  // 210,432 B
    cudaFuncSetAttribute(k_edge, cudaFuncAttributeMaxDynamicSharedMemorySize, edge_smem);

    k_zero<<<2048, 256>>>();

    k_edge<<<148, 256, edge_smem>>>(edge_attr, edge_index,
                                    Wm1, bm1, Wm2, bm2, Wm3, bm3);

    k_ln<<<(N_NODES * 32 + 255) / 256, 256>>>(x, ln_g, ln_b);

    dim3 g1((N_NODES + 63) / 64, (D_U1 + 63) / 64);
    k_gemm<<<g1, 256>>>((const float*)p_nrm, Wu1, bu1, (float*)p_u1,
                        N_NODES, D_U1, D_CAT, 1);

    dim3 g2((N_NODES + 63) / 64, (D_U2 + 63) / 64);
    k_gemm<<<g2, 256>>>((const float*)p_u1, Wu2, bu2, (float*)p_u2,
                        N_NODES, D_U2, D_U1, 1);

    dim3 g3((N_NODES + 63) / 64, (D_OUT + 63) / 64);
    k_gemm<<<g3, 256>>>((const float*)p_u2, Wu3, bu3, out,
                        N_NODES, D_OUT, D_U2, 0);
}

// round 4
// speedup vs baseline: 1.4527x; 1.0132x over previous
#include <cuda_runtime.h>

#define N_NODES 100000
#define N_EDGES 1600000
#define D_F     128
#define D_CAT   256
#define D_U1    214
#define D_U2    172
#define D_OUT   128

#define E_TILE   64
#define N_TILES  (N_EDGES / E_TILE)   // 25000
#define EGRID    148

// k_edge smem layout (float offsets)
#define WSTR 132
#define HSTR 66
#define OFF_W2   0
#define OFF_W3   (OFF_W2 + 128 * WSTR)   // 16896
#define OFF_H    (OFF_W3 + 128 * WSTR)   // 33792
#define OFF_W1   (OFF_H + 128 * HSTR)    // 42240
#define OFF_B1   (OFF_W1 + 640)          // 42880
#define OFF_B2   (OFF_B1 + 128)          // 43008
#define OFF_B3   (OFF_B2 + 128)          // 43136
#define OFF_EA   (OFF_B3 + 128)          // 43264  (2 x 320)
#define OFF_DST  (OFF_EA + 640)          // 43904  (2 x 64 ints)
#define EDGE_SMEM_FLOATS (OFF_DST + 128) // 44032 -> 176,128 B

// ---------------- scratch ----------------
__device__ float g_aggr[N_NODES * D_F];
__device__ float g_nrm [N_NODES * D_CAT];
__device__ float g_u1  [N_NODES * D_U1];
__device__ float g_u2  [N_NODES * D_U2];

// ---------------- helpers ----------------
__device__ __forceinline__ float leaky(float v) { return v > 0.f ? v : 0.01f * v; }

__device__ __forceinline__ unsigned long long pk(float x, float y) {
    unsigned long long r;
    asm("mov.b64 %0, {%1, %2};" : "=l"(r) : "f"(x), "f"(y));
    return r;
}
__device__ __forceinline__ float2 upk(unsigned long long v) {
    float2 f;
    asm("mov.b64 {%0, %1}, %2;" : "=f"(f.x), "=f"(f.y) : "l"(v));
    return f;
}
__device__ __forceinline__ unsigned long long fma2(unsigned long long a,
                                                   unsigned long long b,
                                                   unsigned long long c) {
    unsigned long long d;
    asm("fma.rn.f32x2 %0, %1, %2, %3;" : "=l"(d) : "l"(a), "l"(b), "l"(c));
    return d;
}
__device__ __forceinline__ void red_v4(float* p, float a, float b, float c, float d) {
    asm volatile("red.global.add.v4.f32 [%0], {%1, %2, %3, %4};"
                 :: "l"(p), "f"(a), "f"(b), "f"(c), "f"(d) : "memory");
}

// ---------------- kernel: zero aggr scratch ----------------
__global__ void k_zero() {
    const int n4 = (N_NODES * D_F) / 4;
    float4* p = reinterpret_cast<float4*>(g_aggr);
    for (int i = blockIdx.x * blockDim.x + threadIdx.x; i < n4; i += gridDim.x * blockDim.x)
        p[i] = make_float4(0.f, 0.f, 0.f, 0.f);
}

// ---------------- edge 128x128 layer core ----------------
// warp w: features f0=w*16 (8 f32x2 pairs); lane l: edges e0=2l, e0+1.
__device__ __forceinline__ void edge_mm(
    const float* __restrict__ Wt,    // smem [k][f], stride WSTR
    const float* __restrict__ hin,   // smem [k][e], stride HSTR
    const float* __restrict__ bps,   // smem bias [128]
    unsigned long long acc[8][2],
    int f0, int l)
{
#pragma unroll
    for (int fp = 0; fp < 8; fp++) {
        const unsigned long long b =
            *reinterpret_cast<const unsigned long long*>(&bps[f0 + 2 * fp]);
        acc[fp][0] = b;
        acc[fp][1] = b;
    }
#pragma unroll 4
    for (int k = 0; k < 128; k++) {
        const float* wr = &Wt[k * WSTR + f0];
        const ulonglong2 wA = *reinterpret_cast<const ulonglong2*>(wr);
        const ulonglong2 wB = *reinterpret_cast<const ulonglong2*>(wr + 8);
        const float2 hv = *reinterpret_cast<const float2*>(&hin[k * HSTR + 2 * l]);
        const unsigned long long h0 = pk(hv.x, hv.x);
        const unsigned long long h1 = pk(hv.y, hv.y);
        acc[0][0] = fma2(wA.x, h0, acc[0][0]); acc[0][1] = fma2(wA.x, h1, acc[0][1]);
        acc[1][0] = fma2(wA.y, h0, acc[1][0]); acc[1][1] = fma2(wA.y, h1, acc[1][1]);
        acc[2][0] = fma2(wB.x, h0, acc[2][0]); acc[2][1] = fma2(wB.x, h1, acc[2][1]);
        acc[3][0] = fma2(wB.y, h0, acc[3][0]); acc[3][1] = fma2(wB.y, h1, acc[3][1]);
        const ulonglong2 wC = *reinterpret_cast<const ulonglong2*>(wr + 4);
        const ulonglong2 wD = *reinterpret_cast<const ulonglong2*>(wr + 12);
        acc[4][0] = fma2(wC.x, h0, acc[4][0]); acc[4][1] = fma2(wC.x, h1, acc[4][1]);
        acc[5][0] = fma2(wC.y, h0, acc[5][0]); acc[5][1] = fma2(wC.y, h1, acc[5][1]);
        acc[6][0] = fma2(wD.x, h0, acc[6][0]); acc[6][1] = fma2(wD.x, h1, acc[6][1]);
        acc[7][0] = fma2(wD.y, h0, acc[7][0]); acc[7][1] = fma2(wD.y, h1, acc[7][1]);
    }
}

// NOTE: pair fp covers features (f0+2fp, f0+2fp+1) with the ordering
// acc[0],acc[1] -> f0..f0+3 ; acc[4],acc[5] -> f0+4..f0+7 ;
// acc[2],acc[3] -> f0+8..f0+11 ; acc[6],acc[7] -> f0+12..f0+15
// (wr+8 is fp index 2,3). Keep a map for epilogues:
__device__ __forceinline__ int fp_feat(int fp) {
    // returns feature offset within the 16-feature group for acc pair fp
    const int map[8] = {0, 2, 8, 10, 4, 6, 12, 14};
    return map[fp];
}

// ---------------- kernel: edge MLP + scatter-add ----------------
__global__ void __launch_bounds__(256, 1)
k_edge(const float* __restrict__ edge_attr,
       const int* __restrict__ edge_index,
       const float* __restrict__ Wm1, const float* __restrict__ bm1,
       const float* __restrict__ Wm2, const float* __restrict__ bm2,
       const float* __restrict__ Wm3, const float* __restrict__ bm3)
{
    extern __shared__ float sm[];
    float* W2T = sm + OFF_W2;
    float* W3T = sm + OFF_W3;
    float* hb  = sm + OFF_H;
    float* w1s = sm + OFF_W1;
    float* b1s = sm + OFF_B1;
    float* b2s = sm + OFF_B2;
    float* b3s = sm + OFF_B3;
    float* eab = sm + OFF_EA;                       // [2][320]
    int*   dsb = reinterpret_cast<int*>(sm + OFF_DST); // [2][64]

    const int tid = threadIdx.x;
    const int w   = tid >> 5;
    const int l   = tid & 31;
    const int f0  = w * 16;

    // stage weights transposed [k][f]
    for (int i = tid; i < 128 * 128; i += 256) {
        const int f = i >> 7, k = i & 127;
        W2T[k * WSTR + f] = Wm2[i];
        W3T[k * WSTR + f] = Wm3[i];
    }
    for (int i = tid; i < 640; i += 256) w1s[i] = Wm1[i];
    if (tid < 128) { b1s[tid] = bm1[tid]; b2s[tid] = bm2[tid]; b3s[tid] = bm3[tid]; }

    // ---- prefetch pipeline (depth 2) ----
    const int t0 = blockIdx.x;
    float2 ear = make_float2(0.f, 0.f);
    int    dsr = 0;

    // tile t0 -> buf 0 (direct)
    if (tid < 160) {
        const float2 v = reinterpret_cast<const float2*>(edge_attr + (long long)t0 * E_TILE * 5)[tid];
        reinterpret_cast<float2*>(eab)[tid] = v;
    } else if (tid < 224) {
        dsb[tid - 160] = edge_index[N_EDGES + t0 * E_TILE + (tid - 160)];
    }
    // tile t0+EGRID -> regs
    {
        const int t1 = (t0 + EGRID < N_TILES) ? t0 + EGRID : t0;
        if (tid < 160)
            ear = reinterpret_cast<const float2*>(edge_attr + (long long)t1 * E_TILE * 5)[tid];
        else if (tid < 224)
            dsr = edge_index[N_EDGES + t1 * E_TILE + (tid - 160)];
    }
    __syncthreads();

    int cur = 0;
    for (int tile = t0; tile < N_TILES; tile += EGRID) {
        const float* eas = eab + cur * 320;
        const int*   dsti = dsb + cur * 64;

        // ---- layer 1: 5 -> 128 ----
        {
            const float* ap = &eas[(2 * l) * 5];
            float a[5], b[5];
#pragma unroll
            for (int j = 0; j < 5; j++) { a[j] = ap[j]; b[j] = ap[5 + j]; }
#pragma unroll
            for (int fi = 0; fi < 16; fi++) {
                const int f = f0 + fi;
                float v0 = b1s[f], v1 = v0;
#pragma unroll
                for (int j = 0; j < 5; j++) {
                    const float wv = w1s[f * 5 + j];
                    v0 = fmaf(wv, a[j], v0);
                    v1 = fmaf(wv, b[j], v1);
                }
                *reinterpret_cast<float2*>(&hb[f * HSTR + 2 * l]) =
                    make_float2(leaky(v0), leaky(v1));
            }
        }
        __syncthreads();

        // ---- layer 2: 128 -> 128 (results stay in regs) ----
        unsigned long long acc[8][2];
        edge_mm(W2T, hb, b2s, acc, f0, l);
        __syncthreads();   // all reads of hb done

        // prefetch shuffle: regs -> other buffer, issue next LDG
        {
            const int nb = cur ^ 1;
            if (tid < 160)       reinterpret_cast<float2*>(eab + nb * 320)[tid] = ear;
            else if (tid < 224)  dsb[nb * 64 + (tid - 160)] = dsr;
            const int tn = tile + 2 * EGRID;
            const int tc = (tn < N_TILES) ? tn : t0;
            if (tid < 160)
                ear = reinterpret_cast<const float2*>(edge_attr + (long long)tc * E_TILE * 5)[tid];
            else if (tid < 224)
                dsr = edge_index[N_EDGES + tc * E_TILE + (tid - 160)];
        }

        // write layer-2 output (leaky) back into hb
#pragma unroll
        for (int fp = 0; fp < 8; fp++) {
            const int f = f0 + fp_feat(fp);
            const float2 v0 = upk(acc[fp][0]);   // (f, f+1) @ e0
            const float2 v1 = upk(acc[fp][1]);   // (f, f+1) @ e1
            *reinterpret_cast<float2*>(&hb[f * HSTR + 2 * l]) =
                make_float2(leaky(v0.x), leaky(v1.x));
            *reinterpret_cast<float2*>(&hb[(f + 1) * HSTR + 2 * l]) =
                make_float2(leaky(v0.y), leaky(v1.y));
        }
        __syncthreads();

        // ---- layer 3: 128 -> 128 + vectorized scatter-add ----
        edge_mm(W3T, hb, b3s, acc, f0, l);
        {
            const int d0 = dsti[2 * l];
            const int d1 = dsti[2 * l + 1];
            float* p0 = &g_aggr[(long long)d0 * D_F + f0];
            float* p1 = &g_aggr[(long long)d1 * D_F + f0];
            // acc order -> features: [0][1]=f0..3, [4][5]=f4..7, [2][3]=f8..11, [6][7]=f12..15
            {
                const float2 a0 = upk(acc[0][0]), a1 = upk(acc[1][0]);
                const float2 a2 = upk(acc[4][0]), a3 = upk(acc[5][0]);
                const float2 a4 = upk(acc[2][0]), a5 = upk(acc[3][0]);
                const float2 a6 = upk(acc[6][0]), a7 = upk(acc[7][0]);
                red_v4(p0 + 0,  a0.x, a0.y, a1.x, a1.y);
                red_v4(p0 + 4,  a2.x, a2.y, a3.x, a3.y);
                red_v4(p0 + 8,  a4.x, a4.y, a5.x, a5.y);
                red_v4(p0 + 12, a6.x, a6.y, a7.x, a7.y);
            }
            {
                const float2 a0 = upk(acc[0][1]), a1 = upk(acc[1][1]);
                const float2 a2 = upk(acc[4][1]), a3 = upk(acc[5][1]);
                const float2 a4 = upk(acc[2][1]), a5 = upk(acc[3][1]);
                const float2 a6 = upk(acc[6][1]), a7 = upk(acc[7][1]);
                red_v4(p1 + 0,  a0.x, a0.y, a1.x, a1.y);
                red_v4(p1 + 4,  a2.x, a2.y, a3.x, a3.y);
                red_v4(p1 + 8,  a4.x, a4.y, a5.x, a5.y);
                red_v4(p1 + 12, a6.x, a6.y, a7.x, a7.y);
            }
        }
        __syncthreads();   // hb reads done before next tile's layer-1 writes
        cur ^= 1;
    }
}

// ---------------- kernel: LayerNorm over concat(x, aggr) ----------------
__global__ void k_ln(const float* __restrict__ x,
                     const float* __restrict__ ln_g,
                     const float* __restrict__ ln_b)
{
    const int node = (blockIdx.x * blockDim.x + threadIdx.x) >> 5;
    const int lane = threadIdx.x & 31;
    if (node >= N_NODES) return;

    const float* xr = x      + (long long)node * D_F;
    const float* ar = g_aggr + (long long)node * D_F;
    float v[8];
#pragma unroll
    for (int i = 0; i < 4; i++) v[i]     = xr[lane + 32 * i];
#pragma unroll
    for (int i = 0; i < 4; i++) v[4 + i] = ar[lane + 32 * i];

    float s = 0.f;
#pragma unroll
    for (int i = 0; i < 8; i++) s += v[i];
#pragma unroll
    for (int o = 16; o > 0; o >>= 1) s += __shfl_xor_sync(0xffffffffu, s, o);
    const float mu = s * (1.0f / 256.0f);

    float q = 0.f;
#pragma unroll
    for (int i = 0; i < 8; i++) { const float d = v[i] - mu; q += d * d; }
#pragma unroll
    for (int o = 16; o > 0; o >>= 1) q += __shfl_xor_sync(0xffffffffu, q, o);
    const float rstd = rsqrtf(q * (1.0f / 256.0f) + 1e-5f);

    float* out = g_nrm + (long long)node * D_CAT;
#pragma unroll
    for (int i = 0; i < 8; i++) {
        const int c = (i < 4) ? (lane + 32 * i) : (128 + lane + 32 * (i - 4));
        out[c] = (v[i] - mu) * rstd * ln_g[c] + ln_b[c];
    }
}

// ---------------- kernel: fused GEMM  C = post(A[M,K] @ B[N,K]^T + bias) ----------------
// 128m x 64n tile, 256 threads, 8m x 4n microtile, m-pair f32x2 accumulators,
// B staged duplicated so no pack-MOVs in the inner loop.
#define ASTR 132
#define BSTR 132
__global__ void __launch_bounds__(256)
k_gemm(const float* __restrict__ A, const float* __restrict__ B,
       const float* __restrict__ bias, float* __restrict__ C,
       int M, int N, int K, int doLeaky)
{
    __shared__ float As[16 * ASTR];    // [kk][m 0..127]
    __shared__ float Bd[16 * BSTR];    // [kk][2n dup 0..127]

    const int tid = threadIdx.x;
    const int tx = tid & 15;    // n-quad: n = n0 + tx*4 + {0..3}
    const int ty = tid >> 4;    // m-oct:  m = m0 + ty*8 + {0..7}
    const int m0 = blockIdx.x * 128;
    const int n0 = blockIdx.y * 64;

    unsigned long long acc[4][4];   // [m-pair][n]
#pragma unroll
    for (int i = 0; i < 4; i++)
#pragma unroll
        for (int j = 0; j < 4; j++) acc[i][j] = 0ull;

    for (int k0 = 0; k0 < K; k0 += 16) {
        // stage A [kk][m]
#pragma unroll
        for (int r = 0; r < 8; r++) {
            const int i = tid + r * 256;
            const int mm = i >> 4, kk = i & 15;
            const int ma = m0 + mm, ka = k0 + kk;
            As[kk * ASTR + mm] = (ma < M && ka < K) ? A[(long long)ma * K + ka] : 0.f;
        }
        // stage B duplicated [kk][2n]
#pragma unroll
        for (int r = 0; r < 4; r++) {
            const int i = tid + r * 256;
            const int nn = i >> 4, kk = i & 15;
            const int na = n0 + nn, ka = k0 + kk;
            const float v = (na < N && ka < K) ? B[(long long)na * K + ka] : 0.f;
            *reinterpret_cast<float2*>(&Bd[kk * BSTR + 2 * nn]) = make_float2(v, v);
        }
        __syncthreads();
#pragma unroll
        for (int kk = 0; kk < 16; kk++) {
            const ulonglong2 aA = *reinterpret_cast<const ulonglong2*>(&As[kk * ASTR + ty * 8]);
            const ulonglong2 aB = *reinterpret_cast<const ulonglong2*>(&As[kk * ASTR + ty * 8 + 4]);
            const ulonglong2 bA = *reinterpret_cast<const ulonglong2*>(&Bd[kk * BSTR + tx * 8]);
            const ulonglong2 bB = *reinterpret_cast<const ulonglong2*>(&Bd[kk * BSTR + tx * 8 + 4]);
            // m-pairs: aA.x=(m0,m1) aA.y=(m2,m3) aB.x=(m4,m5) aB.y=(m6,m7)
            // n dups:  bA.x=n0d bA.y=n1d bB.x=n2d bB.y=n3d
            acc[0][0] = fma2(aA.x, bA.x, acc[0][0]);
            acc[0][1] = fma2(aA.x, bA.y, acc[0][1]);
            acc[0][2] = fma2(aA.x, bB.x, acc[0][2]);
            acc[0][3] = fma2(aA.x, bB.y, acc[0][3]);
            acc[1][0] = fma2(aA.y, bA.x, acc[1][0]);
            acc[1][1] = fma2(aA.y, bA.y, acc[1][1]);
            acc[1][2] = fma2(aA.y, bB.x, acc[1][2]);
            acc[1][3] = fma2(aA.y, bB.y, acc[1][3]);
            acc[2][0] = fma2(aB.x, bA.x, acc[2][0]);
            acc[2][1] = fma2(aB.x, bA.y, acc[2][1]);
            acc[2][2] = fma2(aB.x, bB.x, acc[2][2]);
            acc[2][3] = fma2(aB.x, bB.y, acc[2][3]);
            acc[3][0] = fma2(aB.y, bA.x, acc[3][0]);
            acc[3][1] = fma2(aB.y, bA.y, acc[3][1]);
            acc[3][2] = fma2(aB.y, bB.x, acc[3][2]);
            acc[3][3] = fma2(aB.y, bB.y, acc[3][3]);
        }
        __syncthreads();
    }

    // epilogue
#pragma unroll
    for (int mp = 0; mp < 4; mp++) {
        const int m = m0 + ty * 8 + 2 * mp;
#pragma unroll
        for (int j = 0; j < 4; j++) {
            const int n = n0 + tx * 4 + j;
            if (n >= N) continue;
            const float bv = bias[n];
            const float2 v = upk(acc[mp][j]);
            if (m < M) {
                float r = v.x + bv;
                if (doLeaky) r = leaky(r);
                C[(long long)m * N + n] = r;
            }
            if (m + 1 < M) {
                float r = v.y + bv;
                if (doLeaky) r = leaky(r);
                C[(long long)(m + 1) * N + n] = r;
            }
        }
    }
}

// ---------------- launch ----------------
extern "C" void kernel_launch(void* const* d_in, const int* in_sizes, int n_in,
                              void* d_out, int out_size)
{
    const float* x          = (const float*)d_in[0];
    const int*   edge_index = (const int*)d_in[1];
    const float* edge_attr  = (const float*)d_in[2];
    const float* Wm1 = (const float*)d_in[3];
    const float* bm1 = (const float*)d_in[4];
    const float* Wm2 = (const float*)d_in[5];
    const float* bm2 = (const float*)d_in[6];
    const float* Wm3 = (const float*)d_in[7];
    const float* bm3 = (const float*)d_in[8];
    const float* ln_g = (const float*)d_in[9];
    const float* ln_b = (const float*)d_in[10];
    const float* Wu1 = (const float*)d_in[11];
    const float* bu1 = (const float*)d_in[12];
    const float* Wu2 = (const float*)d_in[13];
    const float* bu2 = (const float*)d_in[14];
    const float* Wu3 = (const float*)d_in[15];
    const float* bu3 = (const float*)d_in[16];
    float* out = (float*)d_out;

    void *p_nrm = nullptr, *p_u1 = nullptr, *p_u2 = nullptr;
    cudaGetSymbolAddress(&p_nrm, g_nrm);
    cudaGetSymbolAddress(&p_u1,  g_u1);
    cudaGetSymbolAddress(&p_u2,  g_u2);

    const int edge_smem = EDGE_SMEM_FLOATS * 4;   // 176,128 B
    cudaFuncSetAttribute(k_edge, cudaFuncAttributeMaxDynamicSharedMemorySize, edge_smem);

    k_zero<<<2048, 256>>>();

    k_edge<<<EGRID, 256, edge_smem>>>(edge_attr, edge_index,
                                      Wm1, bm1, Wm2, bm2, Wm3, bm3);

    k_ln<<<(N_NODES * 32 + 255) / 256, 256>>>(x, ln_g, ln_b);

    dim3 g1((N_NODES + 127) / 128, (D_U1 + 63) / 64);
    k_gemm<<<g1, 256>>>((const float*)p_nrm, Wu1, bu1, (float*)p_u1,
                        N_NODES, D_U1, D_CAT, 1);

    dim3 g2((N_NODES + 127) / 128, (D_U2 + 63) / 64);
    k_gemm<<<g2, 256>>>((const float*)p_u1, Wu2, bu2, (float*)p_u2,
                        N_NODES, D_U2, D_U1, 1);

    dim3 g3((N_NODES + 127) / 128, (D_OUT + 63) / 64);
    k_gemm<<<g3, 256>>>((const float*)p_u2, Wu3, bu3, out,
                        N_NODES, D_OUT, D_U2, 0);
}

// round 5
// speedup vs baseline: 1.7860x; 1.2294x over previous
#include <cuda_runtime.h>

#define N_NODES 100000
#define N_EDGES 1600000
#define D_F     128
#define D_CAT   256
#define D_U1    214
#define D_U2    172
#define D_OUT   128

#define E_TILE   128
#define N_TILES  (N_EDGES / E_TILE)   // 12500
#define EGRID    148

// k_edge smem layout (float offsets)
#define WSTR 132
#define HSTR 132
#define OFF_W2   0
#define OFF_W3   (OFF_W2 + 128 * WSTR)   // 16896
#define OFF_H    (OFF_W3 + 128 * WSTR)   // 33792
#define OFF_W1   (OFF_H + 128 * HSTR)    // 50688
#define OFF_B1   (OFF_W1 + 640)          // 51328
#define OFF_B2   (OFF_B1 + 128)          // 51456
#define OFF_B3   (OFF_B2 + 128)          // 51584
#define OFF_EA   (OFF_B3 + 128)          // 51712  (2 x 640)
#define OFF_DST  (OFF_EA + 1280)         // 52992  (2 x 128 ints)
#define EDGE_SMEM_FLOATS (OFF_DST + 256) // 53248 -> 212,992 B

// ---------------- scratch ----------------
__device__ float g_aggr[N_NODES * D_F];
__device__ float g_nrm [N_NODES * D_CAT];
__device__ float g_u1  [N_NODES * D_U1];
__device__ float g_u2  [N_NODES * D_U2];

// ---------------- helpers ----------------
__device__ __forceinline__ float leaky(float v) { return v > 0.f ? v : 0.01f * v; }

__device__ __forceinline__ unsigned long long pk(float x, float y) {
    unsigned long long r;
    asm("mov.b64 %0, {%1, %2};" : "=l"(r) : "f"(x), "f"(y));
    return r;
}
__device__ __forceinline__ float2 upk(unsigned long long v) {
    float2 f;
    asm("mov.b64 {%0, %1}, %2;" : "=f"(f.x), "=f"(f.y) : "l"(v));
    return f;
}
__device__ __forceinline__ unsigned long long fma2(unsigned long long a,
                                                   unsigned long long b,
                                                   unsigned long long c) {
    unsigned long long d;
    asm("fma.rn.f32x2 %0, %1, %2, %3;" : "=l"(d) : "l"(a), "l"(b), "l"(c));
    return d;
}
__device__ __forceinline__ void red_v4(float* p, float a, float b, float c, float d) {
    asm volatile("red.global.add.v4.f32 [%0], {%1, %2, %3, %4};"
                 :: "l"(p), "f"(a), "f"(b), "f"(c), "f"(d) : "memory");
}

// ---------------- kernel: zero aggr scratch ----------------
__global__ void k_zero() {
    const int n4 = (N_NODES * D_F) / 4;
    float4* p = reinterpret_cast<float4*>(g_aggr);
    for (int i = blockIdx.x * blockDim.x + threadIdx.x; i < n4; i += gridDim.x * blockDim.x)
        p[i] = make_float4(0.f, 0.f, 0.f, 0.f);
}

// ---------------- edge 128x128 layer core (128-edge tile) ----------------
// warp w: features f0=w*16 (8 f32x2 pairs); lane l: edges 4l..4l+3.
// acc[fp][ei] covers features (f0+2fp, f0+2fp+1) at edge 4l+ei.
__device__ __forceinline__ void edge_mm(
    const float* __restrict__ Wt,    // smem [k][f], stride WSTR
    const float* __restrict__ hin,   // smem [k][e], stride HSTR
    const float* __restrict__ bps,   // smem bias [128]
    unsigned long long acc[8][4],
    int f0, int l)
{
#pragma unroll
    for (int fp = 0; fp < 8; fp++) {
        const unsigned long long b =
            *reinterpret_cast<const unsigned long long*>(&bps[f0 + 2 * fp]);
#pragma unroll
        for (int ei = 0; ei < 4; ei++) acc[fp][ei] = b;
    }
#pragma unroll 2
    for (int k = 0; k < 128; k++) {
        const float* wr = &Wt[k * WSTR + f0];
        const ulonglong2 wA = *reinterpret_cast<const ulonglong2*>(wr);      // f0..3
        const ulonglong2 wB = *reinterpret_cast<const ulonglong2*>(wr + 4);  // f4..7
        const ulonglong2 wC = *reinterpret_cast<const ulonglong2*>(wr + 8);  // f8..11
        const ulonglong2 wD = *reinterpret_cast<const ulonglong2*>(wr + 12); // f12..15
        const float4 hv = *reinterpret_cast<const float4*>(&hin[k * HSTR + 4 * l]);
        const float he[4] = {hv.x, hv.y, hv.z, hv.w};
#pragma unroll
        for (int ei = 0; ei < 4; ei++) {
            const unsigned long long hh = pk(he[ei], he[ei]);
            acc[0][ei] = fma2(wA.x, hh, acc[0][ei]);
            acc[1][ei] = fma2(wA.y, hh, acc[1][ei]);
            acc[2][ei] = fma2(wB.x, hh, acc[2][ei]);
            acc[3][ei] = fma2(wB.y, hh, acc[3][ei]);
            acc[4][ei] = fma2(wC.x, hh, acc[4][ei]);
            acc[5][ei] = fma2(wC.y, hh, acc[5][ei]);
            acc[6][ei] = fma2(wD.x, hh, acc[6][ei]);
            acc[7][ei] = fma2(wD.y, hh, acc[7][ei]);
        }
    }
}

// ---------------- kernel: edge MLP + scatter-add ----------------
__global__ void __launch_bounds__(256, 1)
k_edge(const float* __restrict__ edge_attr,
       const int* __restrict__ edge_index,
       const float* __restrict__ Wm1, const float* __restrict__ bm1,
       const float* __restrict__ Wm2, const float* __restrict__ bm2,
       const float* __restrict__ Wm3, const float* __restrict__ bm3)
{
    extern __shared__ float sm[];
    float* W2T = sm + OFF_W2;
    float* W3T = sm + OFF_W3;
    float* hb  = sm + OFF_H;
    float* w1s = sm + OFF_W1;
    float* b1s = sm + OFF_B1;
    float* b2s = sm + OFF_B2;
    float* b3s = sm + OFF_B3;
    float* eab = sm + OFF_EA;                          // [2][640]
    int*   dsb = reinterpret_cast<int*>(sm + OFF_DST); // [2][128]

    const int tid = threadIdx.x;
    const int w   = tid >> 5;
    const int l   = tid & 31;
    const int f0  = w * 16;

    // stage weights transposed [k][f]
    for (int i = tid; i < 128 * 128; i += 256) {
        const int f = i >> 7, k = i & 127;
        W2T[k * WSTR + f] = Wm2[i];
        W3T[k * WSTR + f] = Wm3[i];
    }
    for (int i = tid; i < 640; i += 256) w1s[i] = Wm1[i];
    if (tid < 128) { b1s[tid] = bm1[tid]; b2s[tid] = bm2[tid]; b3s[tid] = bm3[tid]; }

    // ---- prefetch pipeline (depth 2) ----
    const int t0 = blockIdx.x;
    float4 ear = make_float4(0.f, 0.f, 0.f, 0.f);
    int    dsr = 0;

    if (tid < 160)
        reinterpret_cast<float4*>(eab)[tid] =
            reinterpret_cast<const float4*>(edge_attr + (long long)t0 * E_TILE * 5)[tid];
    if (tid < 128)
        dsb[tid] = edge_index[N_EDGES + t0 * E_TILE + tid];
    {
        const int t1 = (t0 + EGRID < N_TILES) ? t0 + EGRID : t0;
        if (tid < 160)
            ear = reinterpret_cast<const float4*>(edge_attr + (long long)t1 * E_TILE * 5)[tid];
        if (tid < 128)
            dsr = edge_index[N_EDGES + t1 * E_TILE + tid];
    }
    __syncthreads();

    int cur = 0;
    for (int tile = t0; tile < N_TILES; tile += EGRID) {
        const float* eas  = eab + cur * 640;
        const int*   dsti = dsb + cur * 128;

        // ---- layer 1: 5 -> 128 ----
        {
            float a[20];
            const float4* ap = reinterpret_cast<const float4*>(&eas[(4 * l) * 5]);
#pragma unroll
            for (int q = 0; q < 5; q++) {
                const float4 v = ap[q];
                a[4 * q] = v.x; a[4 * q + 1] = v.y; a[4 * q + 2] = v.z; a[4 * q + 3] = v.w;
            }
#pragma unroll
            for (int fi = 0; fi < 16; fi++) {
                const int f = f0 + fi;
                const float b = b1s[f];
                float v[4];
#pragma unroll
                for (int ei = 0; ei < 4; ei++) {
                    float t = b;
#pragma unroll
                    for (int j = 0; j < 5; j++)
                        t = fmaf(w1s[f * 5 + j], a[ei * 5 + j], t);
                    v[ei] = leaky(t);
                }
                *reinterpret_cast<float4*>(&hb[f * HSTR + 4 * l]) =
                    make_float4(v[0], v[1], v[2], v[3]);
            }
        }
        __syncthreads();

        // ---- layer 2: 128 -> 128 (results stay in regs) ----
        unsigned long long acc[8][4];
        edge_mm(W2T, hb, b2s, acc, f0, l);
        __syncthreads();   // all reads of hb done

        // prefetch shuffle: regs -> other buffer, issue next LDG
        {
            const int nb = cur ^ 1;
            if (tid < 160) reinterpret_cast<float4*>(eab + nb * 640)[tid] = ear;
            if (tid < 128) dsb[nb * 128 + tid] = dsr;
            const int tn = tile + 2 * EGRID;
            const int tc = (tn < N_TILES) ? tn : t0;
            if (tid < 160)
                ear = reinterpret_cast<const float4*>(edge_attr + (long long)tc * E_TILE * 5)[tid];
            if (tid < 128)
                dsr = edge_index[N_EDGES + tc * E_TILE + tid];
        }

        // write layer-2 output (leaky) back into hb
#pragma unroll
        for (int fp = 0; fp < 8; fp++) {
            const int f = f0 + 2 * fp;
            const float2 v0 = upk(acc[fp][0]);
            const float2 v1 = upk(acc[fp][1]);
            const float2 v2 = upk(acc[fp][2]);
            const float2 v3 = upk(acc[fp][3]);
            *reinterpret_cast<float4*>(&hb[f * HSTR + 4 * l]) =
                make_float4(leaky(v0.x), leaky(v1.x), leaky(v2.x), leaky(v3.x));
            *reinterpret_cast<float4*>(&hb[(f + 1) * HSTR + 4 * l]) =
                make_float4(leaky(v0.y), leaky(v1.y), leaky(v2.y), leaky(v3.y));
        }
        __syncthreads();

        // ---- layer 3: 128 -> 128 + vectorized scatter-add ----
        edge_mm(W3T, hb, b3s, acc, f0, l);
#pragma unroll
        for (int ei = 0; ei < 4; ei++) {
            const int d = dsti[4 * l + ei];
            float* p = &g_aggr[(long long)d * D_F + f0];
            const float2 a0 = upk(acc[0][ei]), a1 = upk(acc[1][ei]);
            const float2 a2 = upk(acc[2][ei]), a3 = upk(acc[3][ei]);
            const float2 a4 = upk(acc[4][ei]), a5 = upk(acc[5][ei]);
            const float2 a6 = upk(acc[6][ei]), a7 = upk(acc[7][ei]);
            red_v4(p + 0,  a0.x, a0.y, a1.x, a1.y);
            red_v4(p + 4,  a2.x, a2.y, a3.x, a3.y);
            red_v4(p + 8,  a4.x, a4.y, a5.x, a5.y);
            red_v4(p + 12, a6.x, a6.y, a7.x, a7.y);
        }
        __syncthreads();   // hb reads done before next tile's layer-1 writes
        cur ^= 1;
    }
}

// ---------------- kernel: LayerNorm over concat(x, aggr) ----------------
__global__ void k_ln(const float* __restrict__ x,
                     const float* __restrict__ ln_g,
                     const float* __restrict__ ln_b)
{
    const int node = (blockIdx.x * blockDim.x + threadIdx.x) >> 5;
    const int lane = threadIdx.x & 31;
    if (node >= N_NODES) return;

    const float* xr = x      + (long long)node * D_F;
    const float* ar = g_aggr + (long long)node * D_F;
    float v[8];
#pragma unroll
    for (int i = 0; i < 4; i++) v[i]     = xr[lane + 32 * i];
#pragma unroll
    for (int i = 0; i < 4; i++) v[4 + i] = ar[lane + 32 * i];

    float s = 0.f;
#pragma unroll
    for (int i = 0; i < 8; i++) s += v[i];
#pragma unroll
    for (int o = 16; o > 0; o >>= 1) s += __shfl_xor_sync(0xffffffffu, s, o);
    const float mu = s * (1.0f / 256.0f);

    float q = 0.f;
#pragma unroll
    for (int i = 0; i < 8; i++) { const float d = v[i] - mu; q += d * d; }
#pragma unroll
    for (int o = 16; o > 0; o >>= 1) q += __shfl_xor_sync(0xffffffffu, q, o);
    const float rstd = rsqrtf(q * (1.0f / 256.0f) + 1e-5f);

    float* out = g_nrm + (long long)node * D_CAT;
#pragma unroll
    for (int i = 0; i < 8; i++) {
        const int c = (i < 4) ? (lane + 32 * i) : (128 + lane + 32 * (i - 4));
        out[c] = (v[i] - mu) * rstd * ln_g[c] + ln_b[c];
    }
}

// ---------------- kernel: fused GEMM (round-3 known-good version) ----------------
// 64x64 tile, 256 threads, 4x4 microtile.
__global__ void __launch_bounds__(256)
k_gemm(const float* __restrict__ A, const float* __restrict__ B,
       const float* __restrict__ bias, float* __restrict__ C,
       int M, int N, int K, int doLeaky)
{
    __shared__ float As[16][68];
    __shared__ float Bs[16][68];

    const int tid = threadIdx.x;
    const int tx = tid & 15;
    const int ty = tid >> 4;
    const int m0 = blockIdx.x * 64;
    const int n0 = blockIdx.y * 64;

    unsigned long long acc[4][2];
#pragma unroll
    for (int i = 0; i < 4; i++) { acc[i][0] = pk(0.f, 0.f); acc[i][1] = pk(0.f, 0.f); }

    for (int k0 = 0; k0 < K; k0 += 16) {
#pragma unroll
        for (int r = 0; r < 4; r++) {
            const int i = tid + r * 256;
            const int mm = i >> 4, kk = i & 15;
            const int ka = k0 + kk;
            const int ma = m0 + mm;
            const int na = n0 + mm;
            As[kk][mm] = (ma < M && ka < K) ? A[(long long)ma * K + ka] : 0.f;
            Bs[kk][mm] = (na < N && ka < K) ? B[(long long)na * K + ka] : 0.f;
        }
        __syncthreads();
#pragma unroll
        for (int kk = 0; kk < 16; kk++) {
            const float4 a4 = *reinterpret_cast<const float4*>(&As[kk][ty * 4]);
            const ulonglong2 b2 = *reinterpret_cast<const ulonglong2*>(&Bs[kk][tx * 4]);
            const float av[4] = {a4.x, a4.y, a4.z, a4.w};
#pragma unroll
            for (int i = 0; i < 4; i++) {
                const unsigned long long aa = pk(av[i], av[i]);
                acc[i][0] = fma2(b2.x, aa, acc[i][0]);
                acc[i][1] = fma2(b2.y, aa, acc[i][1]);
            }
        }
        __syncthreads();
    }

    const int nb = n0 + tx * 4;
#pragma unroll
    for (int i = 0; i < 4; i++) {
        const int m = m0 + ty * 4 + i;
        if (m >= M) continue;
        const float2 c0 = upk(acc[i][0]);
        const float2 c1 = upk(acc[i][1]);
        float cv[4] = {c0.x, c0.y, c1.x, c1.y};
#pragma unroll
        for (int j = 0; j < 4; j++) {
            const int n = nb + j;
            if (n < N) {
                float val = cv[j] + bias[n];
                if (doLeaky) val = leaky(val);
                C[(long long)m * N + n] = val;
            }
        }
    }
}

// ---------------- launch ----------------
extern "C" void kernel_launch(void* const* d_in, const int* in_sizes, int n_in,
                              void* d_out, int out_size)
{
    const float* x          = (const float*)d_in[0];
    const int*   edge_index = (const int*)d_in[1];
    const float* edge_attr  = (const float*)d_in[2];
    const float* Wm1 = (const float*)d_in[3];
    const float* bm1 = (const float*)d_in[4];
    const float* Wm2 = (const float*)d_in[5];
    const float* bm2 = (const float*)d_in[6];
    const float* Wm3 = (const float*)d_in[7];
    const float* bm3 = (const float*)d_in[8];
    const float* ln_g = (const float*)d_in[9];
    const float* ln_b = (const float*)d_in[10];
    const float* Wu1 = (const float*)d_in[11];
    const float* bu1 = (const float*)d_in[12];
    const float* Wu2 = (const float*)d_in[13];
    const float* bu2 = (const float*)d_in[14];
    const float* Wu3 = (const float*)d_in[15];
    const float* bu3 = (const float*)d_in[16];
    float* out = (float*)d_out;

    void *p_nrm = nullptr, *p_u1 = nullptr, *p_u2 = nullptr;
    cudaGetSymbolAddress(&p_nrm, g_nrm);
    cudaGetSymbolAddress(&p_u1,  g_u1);
    cudaGetSymbolAddress(&p_u2,  g_u2);

    const int edge_smem = EDGE_SMEM_FLOATS * 4;   // 212,992 B
    cudaFuncSetAttribute(k_edge, cudaFuncAttributeMaxDynamicSharedMemorySize, edge_smem);

    k_zero<<<2048, 256>>>();

    k_edge<<<EGRID, 256, edge_smem>>>(edge_attr, edge_index,
                                      Wm1, bm1, Wm2, bm2, Wm3, bm3);

    k_ln<<<(N_NODES * 32 + 255) / 256, 256>>>(x, ln_g, ln_b);

    dim3 g1((N_NODES + 63) / 64, (D_U1 + 63) / 64);
    k_gemm<<<g1, 256>>>((const float*)p_nrm, Wu1, bu1, (float*)p_u1,
                        N_NODES, D_U1, D_CAT, 1);

    dim3 g2((N_NODES + 63) / 64, (D_U2 + 63) / 64);
    k_gemm<<<g2, 256>>>((const float*)p_u1, Wu2, bu2, (float*)p_u2,
                        N_NODES, D_U2, D_U1, 1);

    dim3 g3((N_NODES + 63) / 64, (D_OUT + 63) / 64);
    k_gemm<<<g3, 256>>>((const float*)p_u2, Wu3, bu3, out,
                        N_NODES, D_OUT, D_U2, 0);
}

// round 7
// speedup vs baseline: 2.1486x; 1.2030x over previous
#include <cuda_runtime.h>
#include <mma.h>

using namespace nvcuda;

#define N_NODES 100000
#define N_EDGES 1600000
#define D_F     128
#define D_CAT   256
#define D_U1    214
#define D_U2    172
#define D_OUT   128

#define E_TILE   128
#define N_TILES  (N_EDGES / E_TILE)   // 12500
#define EGRID    148
#define HP 136                        // h pitch (floats)

// ---- k_edge dynamic smem byte offsets ----
#define SB_H1   0                     // h1 [128][HP] : 69632 B
#define SB_H2   69632                 // h2 [128][HP] : 69632 B
#define SB_WST  139264                // weight staging [128][128] f32: 65536 B
#define SB_W1   204800                // 640 floats
#define SB_B1   207360
#define SB_B2   207872
#define SB_B3   208384
#define SB_EA   208896                // 2 x 640 floats
#define SB_DST  214016                // 2 x 128 ints
#define EDGE_SMEM_BYTES 215040

// ---------------- scratch ----------------
__device__ float g_aggr[N_NODES * D_F];
__device__ float g_nrm [N_NODES * D_CAT];
__device__ float g_u1  [N_NODES * D_U1];
__device__ float g_u2  [N_NODES * D_U2];

// ---------------- helpers ----------------
__device__ __forceinline__ float leaky(float v) { return v > 0.f ? v : 0.01f * v; }

__device__ __forceinline__ unsigned long long pk(float x, float y) {
    unsigned long long r;
    asm("mov.b64 %0, {%1, %2};" : "=l"(r) : "f"(x), "f"(y));
    return r;
}
__device__ __forceinline__ float2 upk(unsigned long long v) {
    float2 f;
    asm("mov.b64 {%0, %1}, %2;" : "=f"(f.x), "=f"(f.y) : "l"(v));
    return f;
}
__device__ __forceinline__ unsigned long long fma2(unsigned long long a,
                                                   unsigned long long b,
                                                   unsigned long long c) {
    unsigned long long d;
    asm("fma.rn.f32x2 %0, %1, %2, %3;" : "=l"(d) : "l"(a), "l"(b), "l"(c));
    return d;
}
__device__ __forceinline__ float tf32f(float x) {
    unsigned r; asm("cvt.rna.tf32.f32 %0, %1;" : "=r"(r) : "f"(x));
    return __uint_as_float(r);
}
__device__ __forceinline__ void red_f32(float* p, float v) {
    asm volatile("red.global.add.f32 [%0], %1;" :: "l"(p), "f"(v) : "memory");
}

// ---------------- kernel: zero aggr scratch ----------------
__global__ void k_zero() {
    const int n4 = (N_NODES * D_F) / 4;
    float4* p = reinterpret_cast<float4*>(g_aggr);
    for (int i = blockIdx.x * blockDim.x + threadIdx.x; i < n4; i += gridDim.x * blockDim.x)
        p[i] = make_float4(0.f, 0.f, 0.f, 0.f);
}

// ---------------- kernel: edge MLP (wmma tf32) + scatter-add ----------------
__global__ void __launch_bounds__(256, 1)
k_edge(const float* __restrict__ edge_attr,
       const int* __restrict__ edge_index,
       const float* __restrict__ Wm1, const float* __restrict__ bm1,
       const float* __restrict__ Wm2, const float* __restrict__ bm2,
       const float* __restrict__ Wm3, const float* __restrict__ bm3)
{
    extern __shared__ char smem[];
    float* h1  = reinterpret_cast<float*>(smem + SB_H1);
    float* h2  = reinterpret_cast<float*>(smem + SB_H2);
    float* wst = reinterpret_cast<float*>(smem + SB_WST);
    float* w1s = reinterpret_cast<float*>(smem + SB_W1);
    float* b1s = reinterpret_cast<float*>(smem + SB_B1);
    float* b2s = reinterpret_cast<float*>(smem + SB_B2);
    float* b3s = reinterpret_cast<float*>(smem + SB_B3);
    float* eab = reinterpret_cast<float*>(smem + SB_EA);
    int*   dsb = reinterpret_cast<int*>(smem + SB_DST);

    const int tid = threadIdx.x;
    const int w   = tid >> 5;
    const int l   = tid & 31;
    const int f0  = w * 16;

    // small params
    for (int i = tid; i < 640; i += 256) w1s[i] = Wm1[i];
    if (tid < 128) { b1s[tid] = bm1[tid]; b2s[tid] = bm2[tid]; b3s[tid] = bm3[tid]; }

    // ---- stage W2 (tf32) and load persistent A fragments ----
    wmma::fragment<wmma::matrix_a, 16, 16, 8, wmma::precision::tf32, wmma::row_major> a2[16], a3[16];
    for (int i = tid; i < 128 * 128; i += 256) wst[i] = tf32f(Wm2[i]);
    __syncthreads();
#pragma unroll
    for (int kt = 0; kt < 16; kt++)
        wmma::load_matrix_sync(a2[kt], wst + f0 * 128 + kt * 8, 128);
    __syncthreads();
    for (int i = tid; i < 128 * 128; i += 256) wst[i] = tf32f(Wm3[i]);
    __syncthreads();
#pragma unroll
    for (int kt = 0; kt < 16; kt++)
        wmma::load_matrix_sync(a3[kt], wst + f0 * 128 + kt * 8, 128);

    // ---- prefetch (depth 2) ----
    const int t0 = blockIdx.x;
    float4 ear = make_float4(0.f, 0.f, 0.f, 0.f);
    int    dsr = 0;
    if (tid < 160)
        reinterpret_cast<float4*>(eab)[tid] =
            reinterpret_cast<const float4*>(edge_attr + (long long)t0 * E_TILE * 5)[tid];
    if (tid < 128)
        dsb[tid] = edge_index[N_EDGES + t0 * E_TILE + tid];
    {
        const int t1 = (t0 + EGRID < N_TILES) ? t0 + EGRID : t0;
        if (tid < 160)
            ear = reinterpret_cast<const float4*>(edge_attr + (long long)t1 * E_TILE * 5)[tid];
        if (tid < 128)
            dsr = edge_index[N_EDGES + t1 * E_TILE + tid];
    }
    __syncthreads();

    // epilogue/scatter mapping
    const int fRow = (w & 3) * 32 + l;
    const int es0  = (w >> 2) * 64;
    // transform mapping (within a 16f x 16e block)
    const int tr_r = l & 15;
    const int tr_c = (l >> 4) * 8;

    int cur = 0;
    for (int tile = t0; tile < N_TILES; tile += EGRID) {
        const float* eas  = eab + cur * 640;
        const int*   dsti = dsb + cur * 128;

        // ---- layer 1: 5 -> 128, write h1[k=f][e] (tf32) ----
        {
            float a[20];
            const float4* ap = reinterpret_cast<const float4*>(&eas[(4 * l) * 5]);
#pragma unroll
            for (int q = 0; q < 5; q++) {
                const float4 v = ap[q];
                a[4*q] = v.x; a[4*q+1] = v.y; a[4*q+2] = v.z; a[4*q+3] = v.w;
            }
#pragma unroll
            for (int fi = 0; fi < 16; fi++) {
                const int f = f0 + fi;
                const float bb = b1s[f];
                float v[4];
#pragma unroll
                for (int ei = 0; ei < 4; ei++) {
                    float t = bb;
#pragma unroll
                    for (int j = 0; j < 5; j++)
                        t = fmaf(w1s[f * 5 + j], a[ei * 5 + j], t);
                    v[ei] = tf32f(leaky(t));
                }
                *reinterpret_cast<float4*>(&h1[f * HP + 4 * l]) =
                    make_float4(v[0], v[1], v[2], v[3]);
            }
        }
        __syncthreads();

        // ---- layer 2: h2 = tf32(leaky(W2 @ h1 + b2)) ----
#pragma unroll 1
        for (int n = 0; n < 8; n++) {
            wmma::fragment<wmma::accumulator, 16, 16, 8, float> acc;
            wmma::fill_fragment(acc, 0.f);
#pragma unroll
            for (int kt = 0; kt < 16; kt++) {
                wmma::fragment<wmma::matrix_b, 16, 16, 8, wmma::precision::tf32, wmma::row_major> bf;
                wmma::load_matrix_sync(bf, h1 + kt * 8 * HP + n * 16, HP);
                wmma::mma_sync(acc, a2[kt], bf, acc);
            }
            wmma::store_matrix_sync(h2 + f0 * HP + n * 16, acc, HP, wmma::mem_row_major);
            __syncwarp();
            // in-place transform: bias + leaky + tf32
            float* p = h2 + (f0 + tr_r) * HP + n * 16 + tr_c;
            const float bv = b2s[f0 + tr_r];
            float4 v0 = *reinterpret_cast<float4*>(p);
            float4 v1 = *reinterpret_cast<float4*>(p + 4);
            v0.x = tf32f(leaky(v0.x + bv)); v0.y = tf32f(leaky(v0.y + bv));
            v0.z = tf32f(leaky(v0.z + bv)); v0.w = tf32f(leaky(v0.w + bv));
            v1.x = tf32f(leaky(v1.x + bv)); v1.y = tf32f(leaky(v1.y + bv));
            v1.z = tf32f(leaky(v1.z + bv)); v1.w = tf32f(leaky(v1.w + bv));
            *reinterpret_cast<float4*>(p)     = v0;
            *reinterpret_cast<float4*>(p + 4) = v1;
        }
        __syncthreads();

        // prefetch shuffle: regs -> other buffer, issue next LDG
        {
            const int nb = cur ^ 1;
            if (tid < 160) reinterpret_cast<float4*>(eab + nb * 640)[tid] = ear;
            if (tid < 128) dsb[nb * 128 + tid] = dsr;
            const int tn = tile + 2 * EGRID;
            const int tc = (tn < N_TILES) ? tn : t0;
            if (tid < 160)
                ear = reinterpret_cast<const float4*>(edge_attr + (long long)tc * E_TILE * 5)[tid];
            if (tid < 128)
                dsr = edge_index[N_EDGES + tc * E_TILE + tid];
        }

        // ---- layer 3: msg = W3 @ h2 (bias at scatter), store into h1 ----
#pragma unroll 1
        for (int n = 0; n < 8; n++) {
            wmma::fragment<wmma::accumulator, 16, 16, 8, float> acc;
            wmma::fill_fragment(acc, 0.f);
#pragma unroll
            for (int kt = 0; kt < 16; kt++) {
                wmma::fragment<wmma::matrix_b, 16, 16, 8, wmma::precision::tf32, wmma::row_major> bf;
                wmma::load_matrix_sync(bf, h2 + kt * 8 * HP + n * 16, HP);
                wmma::mma_sync(acc, a3[kt], bf, acc);
            }
            wmma::store_matrix_sync(h1 + f0 * HP + n * 16, acc, HP, wmma::mem_row_major);
        }
        __syncthreads();

        // ---- scatter: coalesced red.global.add per edge ----
        {
            const float bv = b3s[fRow];
            const float* mrow = h1 + fRow * HP;
#pragma unroll 4
            for (int j = 0; j < 64; j++) {
                const int e = es0 + j;
                const int d = dsti[e];
                red_f32(&g_aggr[(long long)d * D_F + fRow], mrow[e] + bv);
            }
        }
        __syncthreads();
        cur ^= 1;
    }
}

// ---------------- kernel: LayerNorm over concat(x, aggr) ----------------
__global__ void k_ln(const float* __restrict__ x,
                     const float* __restrict__ ln_g,
                     const float* __restrict__ ln_b)
{
    const int node = (blockIdx.x * blockDim.x + threadIdx.x) >> 5;
    const int lane = threadIdx.x & 31;
    if (node >= N_NODES) return;

    const float* xr = x      + (long long)node * D_F;
    const float* ar = g_aggr + (long long)node * D_F;
    float v[8];
#pragma unroll
    for (int i = 0; i < 4; i++) v[i]     = xr[lane + 32 * i];
#pragma unroll
    for (int i = 0; i < 4; i++) v[4 + i] = ar[lane + 32 * i];

    float s = 0.f;
#pragma unroll
    for (int i = 0; i < 8; i++) s += v[i];
#pragma unroll
    for (int o = 16; o > 0; o >>= 1) s += __shfl_xor_sync(0xffffffffu, s, o);
    const float mu = s * (1.0f / 256.0f);

    float q = 0.f;
#pragma unroll
    for (int i = 0; i < 8; i++) { const float d = v[i] - mu; q += d * d; }
#pragma unroll
    for (int o = 16; o > 0; o >>= 1) q += __shfl_xor_sync(0xffffffffu, q, o);
    const float rstd = rsqrtf(q * (1.0f / 256.0f) + 1e-5f);

    float* out = g_nrm + (long long)node * D_CAT;
#pragma unroll
    for (int i = 0; i < 8; i++) {
        const int c = (i < 4) ? (lane + 32 * i) : (128 + lane + 32 * (i - 4));
        out[c] = (v[i] - mu) * rstd * ln_g[c] + ln_b[c];
    }
}

// ---------------- kernel: fused GEMM (known-good) ----------------
__global__ void __launch_bounds__(256)
k_gemm(const float* __restrict__ A, const float* __restrict__ B,
       const float* __restrict__ bias, float* __restrict__ C,
       int M, int N, int K, int doLeaky)
{
    __shared__ float As[16][68];
    __shared__ float Bs[16][68];

    const int tid = threadIdx.x;
    const int tx = tid & 15;
    const int ty = tid >> 4;
    const int m0 = blockIdx.x * 64;
    const int n0 = blockIdx.y * 64;

    unsigned long long acc[4][2];
#pragma unroll
    for (int i = 0; i < 4; i++) { acc[i][0] = pk(0.f, 0.f); acc[i][1] = pk(0.f, 0.f); }

    for (int k0 = 0; k0 < K; k0 += 16) {
#pragma unroll
        for (int r = 0; r < 4; r++) {
            const int i = tid + r * 256;
            const int mm = i >> 4, kk = i & 15;
            const int ka = k0 + kk;
            const int ma = m0 + mm;
            const int na = n0 + mm;
            As[kk][mm] = (ma < M && ka < K) ? A[(long long)ma * K + ka] : 0.f;
            Bs[kk][mm] = (na < N && ka < K) ? B[(long long)na * K + ka] : 0.f;
        }
        __syncthreads();
#pragma unroll
        for (int kk = 0; kk < 16; kk++) {
            const float4 a4 = *reinterpret_cast<const float4*>(&As[kk][ty * 4]);
            const ulonglong2 b2 = *reinterpret_cast<const ulonglong2*>(&Bs[kk][tx * 4]);
            const float av[4] = {a4.x, a4.y, a4.z, a4.w};
#pragma unroll
            for (int i = 0; i < 4; i++) {
                const unsigned long long aa = pk(av[i], av[i]);
                acc[i][0] = fma2(b2.x, aa, acc[i][0]);
                acc[i][1] = fma2(b2.y, aa, acc[i][1]);
            }
        }
        __syncthreads();
    }

    const int nb = n0 + tx * 4;
#pragma unroll
    for (int i = 0; i < 4; i++) {
        const int m = m0 + ty * 4 + i;
        if (m >= M) continue;
        const float2 c0 = upk(acc[i][0]);
        const float2 c1 = upk(acc[i][1]);
        float cv[4] = {c0.x, c0.y, c1.x, c1.y};
#pragma unroll
        for (int j = 0; j < 4; j++) {
            const int n = nb + j;
            if (n < N) {
                float val = cv[j] + bias[n];
                if (doLeaky) val = leaky(val);
                C[(long long)m * N + n] = val;
            }
        }
    }
}

// ---------------- launch ----------------
extern "C" void kernel_launch(void* const* d_in, const int* in_sizes, int n_in,
                              void* d_out, int out_size)
{
    const float* x          = (const float*)d_in[0];
    const int*   edge_index = (const int*)d_in[1];
    const float* edge_attr  = (const float*)d_in[2];
    const float* Wm1 = (const float*)d_in[3];
    const float* bm1 = (const float*)d_in[4];
    const float* Wm2 = (const float*)d_in[5];
    const float* bm2 = (const float*)d_in[6];
    const float* Wm3 = (const float*)d_in[7];
    const float* bm3 = (const float*)d_in[8];
    const float* ln_g = (const float*)d_in[9];
    const float* ln_b = (const float*)d_in[10];
    const float* Wu1 = (const float*)d_in[11];
    const float* bu1 = (const float*)d_in[12];
    const float* Wu2 = (const float*)d_in[13];
    const float* bu2 = (const float*)d_in[14];
    const float* Wu3 = (const float*)d_in[15];
    const float* bu3 = (const float*)d_in[16];
    float* out = (float*)d_out;

    void *p_nrm = nullptr, *p_u1 = nullptr, *p_u2 = nullptr;
    cudaGetSymbolAddress(&p_nrm, g_nrm);
    cudaGetSymbolAddress(&p_u1,  g_u1);
    cudaGetSymbolAddress(&p_u2,  g_u2);

    cudaFuncSetAttribute(k_edge, cudaFuncAttributeMaxDynamicSharedMemorySize, EDGE_SMEM_BYTES);

    k_zero<<<2048, 256>>>();

    k_edge<<<EGRID, 256, EDGE_SMEM_BYTES>>>(edge_attr, edge_index,
                                            Wm1, bm1, Wm2, bm2, Wm3, bm3);

    k_ln<<<(N_NODES * 32 + 255) / 256, 256>>>(x, ln_g, ln_b);

    dim3 g1((N_NODES + 63) / 64, (D_U1 + 63) / 64);
    k_gemm<<<g1, 256>>>((const float*)p_nrm, Wu1, bu1, (float*)p_u1,
                        N_NODES, D_U1, D_CAT, 1);

    dim3 g2((N_NODES + 63) / 64, (D_U2 + 63) / 64);
    k_gemm<<<g2, 256>>>((const float*)p_u1, Wu2, bu2, (float*)p_u2,
                        N_NODES, D_U2, D_U1, 1);

    dim3 g3((N_NODES + 63) / 64, (D_OUT + 63) / 64);
    k_gemm<<<g3, 256>>>((const float*)p_u2, Wu3, bu3, out,
                        N_NODES, D_OUT, D_U2, 0);
}

// round 8
// speedup vs baseline: 2.2425x; 1.0437x over previous
#include <cuda_runtime.h>
#include <mma.h>

using namespace nvcuda;

#define N_NODES 100000
#define N_EDGES 1600000
#define D_F     128
#define D_CAT   256
#define D_U1    214
#define D_U2    172
#define D_OUT   128

#define E_TILE   128
#define N_TILES  (N_EDGES / E_TILE)   // 12500
#define EGRID    148
#define HP 136                        // h pitch (floats)

// ---- k_edge dynamic smem byte offsets ----
#define SB_H1   0                     // h1 [128][HP] : 69632 B
#define SB_H2   69632                 // h2 [128][HP] : 69632 B
#define SB_WST  139264                // weight staging / bias mats : 65536 B
#define SB_W1   204800                // 640 floats
#define SB_B1   207360
#define SB_B2   207872
#define SB_B3   208384
#define SB_EA   208896                // 2 x 640 floats
#define SB_DST  214016                // 2 x 128 ints
#define EDGE_SMEM_BYTES 215040

// ---------------- scratch ----------------
__device__ float g_aggr[N_NODES * D_F];
__device__ float g_nrm [N_NODES * D_CAT];
__device__ float g_u1  [N_NODES * D_U1];
__device__ float g_u2  [N_NODES * D_U2];

// ---------------- helpers ----------------
__device__ __forceinline__ float leaky(float v) { return v > 0.f ? v : 0.01f * v; }

__device__ __forceinline__ float tf32f(float x) {
    unsigned r; asm("cvt.rna.tf32.f32 %0, %1;" : "=r"(r) : "f"(x));
    return __uint_as_float(r);
}
__device__ __forceinline__ void red_f32(float* p, float v) {
    asm volatile("red.global.add.f32 [%0], %1;" :: "l"(p), "f"(v) : "memory");
}

// ---------------- kernel: zero aggr scratch ----------------
__global__ void k_zero() {
    const int n4 = (N_NODES * D_F) / 4;
    float4* p = reinterpret_cast<float4*>(g_aggr);
    for (int i = blockIdx.x * blockDim.x + threadIdx.x; i < n4; i += gridDim.x * blockDim.x)
        p[i] = make_float4(0.f, 0.f, 0.f, 0.f);
}

// ---------------- kernel: edge MLP (wmma tf32) + scatter-add ----------------
__global__ void __launch_bounds__(256, 1)
k_edge(const float* __restrict__ edge_attr,
       const int* __restrict__ edge_index,
       const float* __restrict__ Wm1, const float* __restrict__ bm1,
       const float* __restrict__ Wm2, const float* __restrict__ bm2,
       const float* __restrict__ Wm3, const float* __restrict__ bm3)
{
    extern __shared__ char smem[];
    float* h1  = reinterpret_cast<float*>(smem + SB_H1);
    float* h2  = reinterpret_cast<float*>(smem + SB_H2);
    float* wst = reinterpret_cast<float*>(smem + SB_WST);
    float* w1s = reinterpret_cast<float*>(smem + SB_W1);
    float* b1s = reinterpret_cast<float*>(smem + SB_B1);
    float* b2s = reinterpret_cast<float*>(smem + SB_B2);
    float* b3s = reinterpret_cast<float*>(smem + SB_B3);
    float* eab = reinterpret_cast<float*>(smem + SB_EA);
    int*   dsb = reinterpret_cast<int*>(smem + SB_DST);

    const int tid = threadIdx.x;
    const int w   = tid >> 5;
    const int l   = tid & 31;
    const int f0  = w * 16;

    // small params
    for (int i = tid; i < 640; i += 256) w1s[i] = Wm1[i];
    if (tid < 128) { b1s[tid] = bm1[tid]; b2s[tid] = bm2[tid]; b3s[tid] = bm3[tid]; }

    // ---- stage W2/W3 (tf32) and load persistent A fragments ----
    wmma::fragment<wmma::matrix_a, 16, 16, 8, wmma::precision::tf32, wmma::row_major> a2[16], a3[16];
    for (int i = tid; i < 128 * 128; i += 256) wst[i] = tf32f(Wm2[i]);
    __syncthreads();
#pragma unroll
    for (int kt = 0; kt < 16; kt++)
        wmma::load_matrix_sync(a2[kt], wst + f0 * 128 + kt * 8, 128);
    __syncthreads();
    for (int i = tid; i < 128 * 128; i += 256) wst[i] = tf32f(Wm3[i]);
    __syncthreads();
#pragma unroll
    for (int kt = 0; kt < 16; kt++)
        wmma::load_matrix_sync(a3[kt], wst + f0 * 128 + kt * 8, 128);
    __syncthreads();

    // ---- persistent bias accumulator fragments (rows = f, bcast over cols) ----
    float* bm2m = wst;          // [128][16]
    float* bm3m = wst + 2048;   // [128][16]
    for (int i = tid; i < 128 * 16; i += 256) {
        const int f = i >> 4;
        bm2m[i] = b2s[f];
        bm3m[i] = b3s[f];
    }
    __syncthreads();
    wmma::fragment<wmma::accumulator, 16, 16, 8, float> ab2, ab3;
    wmma::load_matrix_sync(ab2, bm2m + f0 * 16, 16, wmma::mem_row_major);
    wmma::load_matrix_sync(ab3, bm3m + f0 * 16, 16, wmma::mem_row_major);

    // ---- prefetch (depth 2) ----
    const int t0 = blockIdx.x;
    float4 ear = make_float4(0.f, 0.f, 0.f, 0.f);
    int    dsr = 0;
    if (tid < 160)
        reinterpret_cast<float4*>(eab)[tid] =
            reinterpret_cast<const float4*>(edge_attr + (long long)t0 * E_TILE * 5)[tid];
    if (tid < 128)
        dsb[tid] = edge_index[N_EDGES + t0 * E_TILE + tid];
    {
        const int t1 = (t0 + EGRID < N_TILES) ? t0 + EGRID : t0;
        if (tid < 160)
            ear = reinterpret_cast<const float4*>(edge_attr + (long long)t1 * E_TILE * 5)[tid];
        if (tid < 128)
            dsr = edge_index[N_EDGES + t1 * E_TILE + tid];
    }
    __syncthreads();

    // scatter mapping
    const int fRow = (w & 3) * 32 + l;
    const int es0  = (w >> 2) * 64;

    int cur = 0;
    for (int tile = t0; tile < N_TILES; tile += EGRID) {
        const float* eas  = eab + cur * 640;
        const int*   dsti = dsb + cur * 128;

        // ---- layer 1: 5 -> 128, write h1[k=f][e] (tf32) ----
        {
            float a[20];
            const float4* ap = reinterpret_cast<const float4*>(&eas[(4 * l) * 5]);
#pragma unroll
            for (int q = 0; q < 5; q++) {
                const float4 v = ap[q];
                a[4*q] = v.x; a[4*q+1] = v.y; a[4*q+2] = v.z; a[4*q+3] = v.w;
            }
#pragma unroll
            for (int fi = 0; fi < 16; fi++) {
                const int f = f0 + fi;
                const float bb = b1s[f];
                float v[4];
#pragma unroll
                for (int ei = 0; ei < 4; ei++) {
                    float t = bb;
#pragma unroll
                    for (int j = 0; j < 5; j++)
                        t = fmaf(w1s[f * 5 + j], a[ei * 5 + j], t);
                    v[ei] = tf32f(leaky(t));
                }
                *reinterpret_cast<float4*>(&h1[f * HP + 4 * l]) =
                    make_float4(v[0], v[1], v[2], v[3]);
            }
        }
        __syncthreads();

        // ---- layer 2: h2 = tf32(leaky(W2 @ h1 + b2)), 2-wide n interleave ----
#pragma unroll 1
        for (int n = 0; n < 8; n += 2) {
            wmma::fragment<wmma::accumulator, 16, 16, 8, float> ac0 = ab2, ac1 = ab2;
#pragma unroll
            for (int kt = 0; kt < 16; kt++) {
                wmma::fragment<wmma::matrix_b, 16, 16, 8, wmma::precision::tf32, wmma::row_major> bf0, bf1;
                wmma::load_matrix_sync(bf0, h1 + kt * 8 * HP + n * 16, HP);
                wmma::load_matrix_sync(bf1, h1 + kt * 8 * HP + n * 16 + 16, HP);
                wmma::mma_sync(ac0, a2[kt], bf0, ac0);
                wmma::mma_sync(ac1, a2[kt], bf1, ac1);
            }
#pragma unroll
            for (int i = 0; i < ac0.num_elements; i++) {
                ac0.x[i] = tf32f(leaky(ac0.x[i]));
                ac1.x[i] = tf32f(leaky(ac1.x[i]));
            }
            wmma::store_matrix_sync(h2 + f0 * HP + n * 16, ac0, HP, wmma::mem_row_major);
            wmma::store_matrix_sync(h2 + f0 * HP + n * 16 + 16, ac1, HP, wmma::mem_row_major);
        }
        __syncthreads();

        // prefetch shuffle: regs -> other buffer, issue next LDG
        {
            const int nb = cur ^ 1;
            if (tid < 160) reinterpret_cast<float4*>(eab + nb * 640)[tid] = ear;
            if (tid < 128) dsb[nb * 128 + tid] = dsr;
            const int tn = tile + 2 * EGRID;
            const int tc = (tn < N_TILES) ? tn : t0;
            if (tid < 160)
                ear = reinterpret_cast<const float4*>(edge_attr + (long long)tc * E_TILE * 5)[tid];
            if (tid < 128)
                dsr = edge_index[N_EDGES + tc * E_TILE + tid];
        }

        // ---- layer 3: msg = W3 @ h2 + b3, store into h1 ----
#pragma unroll 1
        for (int n = 0; n < 8; n += 2) {
            wmma::fragment<wmma::accumulator, 16, 16, 8, float> ac0 = ab3, ac1 = ab3;
#pragma unroll
            for (int kt = 0; kt < 16; kt++) {
                wmma::fragment<wmma::matrix_b, 16, 16, 8, wmma::precision::tf32, wmma::row_major> bf0, bf1;
                wmma::load_matrix_sync(bf0, h2 + kt * 8 * HP + n * 16, HP);
                wmma::load_matrix_sync(bf1, h2 + kt * 8 * HP + n * 16 + 16, HP);
                wmma::mma_sync(ac0, a3[kt], bf0, ac0);
                wmma::mma_sync(ac1, a3[kt], bf1, ac1);
            }
            wmma::store_matrix_sync(h1 + f0 * HP + n * 16, ac0, HP, wmma::mem_row_major);
            wmma::store_matrix_sync(h1 + f0 * HP + n * 16 + 16, ac1, HP, wmma::mem_row_major);
        }
        __syncthreads();

        // ---- scatter: coalesced red.global.add per edge ----
        {
            const float* mrow = h1 + fRow * HP;
#pragma unroll 4
            for (int j = 0; j < 64; j++) {
                const int e = es0 + j;
                const int d = dsti[e];
                red_f32(&g_aggr[(long long)d * D_F + fRow], mrow[e]);
            }
        }
        __syncthreads();
        cur ^= 1;
    }
}

// ---------------- kernel: LayerNorm over concat(x, aggr) ----------------
__global__ void k_ln(const float* __restrict__ x,
                     const float* __restrict__ ln_g,
                     const float* __restrict__ ln_b)
{
    const int node = (blockIdx.x * blockDim.x + threadIdx.x) >> 5;
    const int lane = threadIdx.x & 31;
    if (node >= N_NODES) return;

    const float* xr = x      + (long long)node * D_F;
    const float* ar = g_aggr + (long long)node * D_F;
    float v[8];
#pragma unroll
    for (int i = 0; i < 4; i++) v[i]     = xr[lane + 32 * i];
#pragma unroll
    for (int i = 0; i < 4; i++) v[4 + i] = ar[lane + 32 * i];

    float s = 0.f;
#pragma unroll
    for (int i = 0; i < 8; i++) s += v[i];
#pragma unroll
    for (int o = 16; o > 0; o >>= 1) s += __shfl_xor_sync(0xffffffffu, s, o);
    const float mu = s * (1.0f / 256.0f);

    float q = 0.f;
#pragma unroll
    for (int i = 0; i < 8; i++) { const float d = v[i] - mu; q += d * d; }
#pragma unroll
    for (int o = 16; o > 0; o >>= 1) q += __shfl_xor_sync(0xffffffffu, q, o);
    const float rstd = rsqrtf(q * (1.0f / 256.0f) + 1e-5f);

    float* out = g_nrm + (long long)node * D_CAT;
#pragma unroll
    for (int i = 0; i < 8; i++) {
        const int c = (i < 4) ? (lane + 32 * i) : (128 + lane + 32 * (i - 4));
        out[c] = (v[i] - mu) * rstd * ln_g[c] + ln_b[c];
    }
}

// ---------------- kernel: wmma tf32 GEMM  C = post(A[M,K] @ B[N,K]^T + bias) ----------------
// 64x64 tile, 8 warps (2m x 4n), each warp 32m x 16n.
// Block origin clamped to (M-64, N-64): overlapped blocks write identical values.
__global__ void __launch_bounds__(256)
k_wgemm(const float* __restrict__ A, const float* __restrict__ B,
        const float* __restrict__ bias, float* __restrict__ C,
        int M, int N, int K, int doLeaky)
{
    __shared__ float As[64 * 36];
    __shared__ float Bs[64 * 36];
    __shared__ float bmat[16 * 68];

    const int tid = threadIdx.x;
    const int w  = tid >> 5;
    const int wm = w >> 2;    // 0..1
    const int wn = w & 3;     // 0..3
    int m0 = blockIdx.x * 64; if (m0 > M - 64) m0 = M - 64;
    int n0 = blockIdx.y * 64; if (n0 > N - 64) n0 = N - 64;

    for (int i = tid; i < 16 * 64; i += 256) {
        const int r = i >> 6, c = i & 63;
        bmat[r * 68 + c] = bias[n0 + c];
    }
    __syncthreads();

    wmma::fragment<wmma::accumulator, 16, 16, 8, float> acc0, acc1;
    wmma::load_matrix_sync(acc0, bmat + wn * 16, 68, wmma::mem_row_major);
    acc1 = acc0;
    __syncthreads();

    for (int k0 = 0; k0 < K; k0 += 32) {
#pragma unroll
        for (int r = 0; r < 8; r++) {
            const int i = tid + r * 256;
            const int mm = i >> 5, kk = i & 31;
            const int ka = k0 + kk;
            As[mm * 36 + kk] = (ka < K) ? tf32f(A[(long long)(m0 + mm) * K + ka]) : 0.f;
            Bs[mm * 36 + kk] = (ka < K) ? tf32f(B[(long long)(n0 + mm) * K + ka]) : 0.f;
        }
        __syncthreads();
#pragma unroll
        for (int kt = 0; kt < 4; kt++) {
            wmma::fragment<wmma::matrix_a, 16, 16, 8, wmma::precision::tf32, wmma::row_major> af0, af1;
            wmma::fragment<wmma::matrix_b, 16, 16, 8, wmma::precision::tf32, wmma::col_major> bf;
            wmma::load_matrix_sync(af0, As + (wm * 32) * 36 + kt * 8, 36);
            wmma::load_matrix_sync(af1, As + (wm * 32 + 16) * 36 + kt * 8, 36);
            wmma::load_matrix_sync(bf, Bs + (wn * 16) * 36 + kt * 8, 36);
            wmma::mma_sync(acc0, af0, bf, acc0);
            wmma::mma_sync(acc1, af1, bf, acc1);
        }
        __syncthreads();
    }

    if (doLeaky) {
#pragma unroll
        for (int i = 0; i < acc0.num_elements; i++) {
            acc0.x[i] = leaky(acc0.x[i]);
            acc1.x[i] = leaky(acc1.x[i]);
        }
    }
    wmma::store_matrix_sync(C + (long long)(m0 + wm * 32) * N + n0 + wn * 16,
                            acc0, N, wmma::mem_row_major);
    wmma::store_matrix_sync(C + (long long)(m0 + wm * 32 + 16) * N + n0 + wn * 16,
                            acc1, N, wmma::mem_row_major);
}

// ---------------- launch ----------------
extern "C" void kernel_launch(void* const* d_in, const int* in_sizes, int n_in,
                              void* d_out, int out_size)
{
    const float* x          = (const float*)d_in[0];
    const int*   edge_index = (const int*)d_in[1];
    const float* edge_attr  = (const float*)d_in[2];
    const float* Wm1 = (const float*)d_in[3];
    const float* bm1 = (const float*)d_in[4];
    const float* Wm2 = (const float*)d_in[5];
    const float* bm2 = (const float*)d_in[6];
    const float* Wm3 = (const float*)d_in[7];
    const float* bm3 = (const float*)d_in[8];
    const float* ln_g = (const float*)d_in[9];
    const float* ln_b = (const float*)d_in[10];
    const float* Wu1 = (const float*)d_in[11];
    const float* bu1 = (const float*)d_in[12];
    const float* Wu2 = (const float*)d_in[13];
    const float* bu2 = (const float*)d_in[14];
    const float* Wu3 = (const float*)d_in[15];
    const float* bu3 = (const float*)d_in[16];
    float* out = (float*)d_out;

    void *p_nrm = nullptr, *p_u1 = nullptr, *p_u2 = nullptr;
    cudaGetSymbolAddress(&p_nrm, g_nrm);
    cudaGetSymbolAddress(&p_u1,  g_u1);
    cudaGetSymbolAddress(&p_u2,  g_u2);

    cudaFuncSetAttribute(k_edge, cudaFuncAttributeMaxDynamicSharedMemorySize, EDGE_SMEM_BYTES);

    k_zero<<<2048, 256>>>();

    k_edge<<<EGRID, 256, EDGE_SMEM_BYTES>>>(edge_attr, edge_index,
                                            Wm1, bm1, Wm2, bm2, Wm3, bm3);

    k_ln<<<(N_NODES * 32 + 255) / 256, 256>>>(x, ln_g, ln_b);

    dim3 g1((N_NODES + 63) / 64, (D_U1 + 63) / 64);
    k_wgemm<<<g1, 256>>>((const float*)p_nrm, Wu1, bu1, (float*)p_u1,
                         N_NODES, D_U1, D_CAT, 1);

    dim3 g2((N_NODES + 63) / 64, (D_U2 + 63) / 64);
    k_wgemm<<<g2, 256>>>((const float*)p_u1, Wu2, bu2, (float*)p_u2,
                         N_NODES, D_U2, D_U1, 1);

    dim3 g3((N_NODES + 63) / 64, (D_OUT + 63) / 64);
    k_wgemm<<<g3, 256>>>((const float*)p_u2, Wu3, bu3, out,
                         N_NODES, D_OUT, D_U2, 0);
}